// round 2
// baseline (speedup 1.0000x reference)
#include <cuda_runtime.h>
#include <cuda_fp16.h>

#define BB   128
#define TT   1024
#define NIN  512
#define HH   1024
#define NOUT 256
#define KK   (HH + NIN)          // 1536

#define NCTA 128
#define KC   64
#define SA   72                  // A smem row stride (halves) -> conflict-free frags
#define SW   1544                // W smem row stride (halves)
#define SAY  72

#define SMEM_MAIN (32*SW*2 + 2*BB*SA*2)          // 98816 + 36864 = 135680
#define SMEM_Y    ((BB + NOUT)*SAY*2)            // 55296

// ---------------- device scratch (static; no runtime allocation) ----------------
__device__ __half  g_Wp[(size_t)NCTA * 32 * KK];     // [cta][l=32][k=1536] fp16
__device__ __half  g_u16[(size_t)TT * BB * NIN];     // [t][b][n] fp16
__device__ __half  g_h[2][BB * HH];                  // double-buffered hidden
__device__ __half  g_hist[(size_t)TT * BB * HH];     // h history [t][b][h]
__device__ __half  g_Wy[(size_t)NOUT * HH];          // W_hy^T [n][k]
__device__ unsigned g_cnt;                           // barrier counter (self-restoring)
__device__ unsigned g_phase;                         // barrier epoch (monotonic)

// ---------------- prep ----------------
__global__ void pack_w_kernel(const float* __restrict__ Whf, const float* __restrict__ Whi,
                              const float* __restrict__ Who, const float* __restrict__ Whc,
                              const float* __restrict__ Wuf, const float* __restrict__ Wui,
                              const float* __restrict__ Wuo, const float* __restrict__ Wuc)
{
    __shared__ float tile[32][33];
    int jt = blockIdx.x;            // 0..31   (j tile)
    int kt = blockIdx.y;            // 0..47   (k tile)
    int g  = blockIdx.z;            // 0..3    (gate)
    int tx = threadIdx.x;           // 0..31
    int ty = threadIdx.y;           // 0..7
    const float* Wh = (g == 0) ? Whf : (g == 1) ? Whi : (g == 2) ? Who : Whc;
    const float* Wu = (g == 0) ? Wuf : (g == 1) ? Wui : (g == 2) ? Wuo : Wuc;
    int kbase = kt * 32;
    #pragma unroll
    for (int r = 0; r < 4; ++r) {
        int k = kbase + ty * 4 + r;
        int j = jt * 32 + tx;
        float v = (k < HH) ? Wh[(size_t)k * HH + j] : Wu[(size_t)(k - HH) * HH + j];
        tile[ty * 4 + r][tx] = v;
    }
    __syncthreads();
    #pragma unroll
    for (int r = 0; r < 4; ++r) {
        int jl = ty * 4 + r;
        int j = jt * 32 + jl;
        int row = (j >> 3) * 32 + g * 8 + (j & 7);      // cta = j>>3, l = g*8 + (j&7)
        g_Wp[(size_t)row * KK + kbase + tx] = __float2half_rn(tile[tx][jl]);
    }
}

__global__ void pack_u_kernel(const float* __restrict__ u)
{
    long long idx = (long long)blockIdx.x * blockDim.x + threadIdx.x;
    if (idx >= (long long)BB * TT * NIN) return;
    int n = (int)(idx & (NIN - 1));
    int t = (int)((idx >> 9) & (TT - 1));
    int b = (int)(idx >> 19);
    g_u16[((size_t)t * BB + b) * NIN + n] = __float2half_rn(u[idx]);
}

__global__ void pack_misc_kernel(const float* __restrict__ Why, const float* __restrict__ h0)
{
    int idx = blockIdx.x * blockDim.x + threadIdx.x;
    if (idx < NOUT * HH) {
        int n = idx / HH, k = idx % HH;
        g_Wy[idx] = __float2half_rn(Why[(size_t)k * NOUT + n]);
    }
    if (idx < BB * HH) {
        g_h[0][idx] = __float2half_rn(h0[idx & (HH - 1)]);
    }
}

// ---------------- helpers ----------------
__device__ __forceinline__ void mma16816(float* c, const unsigned* a, unsigned b0, unsigned b1)
{
    asm volatile(
        "mma.sync.aligned.m16n8k16.row.col.f32.f16.f16.f32 "
        "{%0,%1,%2,%3}, {%4,%5,%6,%7}, {%8,%9}, {%0,%1,%2,%3};"
        : "+f"(c[0]), "+f"(c[1]), "+f"(c[2]), "+f"(c[3])
        : "r"(a[0]), "r"(a[1]), "r"(a[2]), "r"(a[3]), "r"(b0), "r"(b1));
}
__device__ __forceinline__ float sigmoidf_(float x) { return 1.0f / (1.0f + __expf(-x)); }

// ---------------- persistent recurrent kernel ----------------
__global__ void __launch_bounds__(256, 1)
lstm_main(const float* __restrict__ bf, const float* __restrict__ bi,
          const float* __restrict__ bo, const float* __restrict__ bc)
{
    extern __shared__ char sm[];
    __half* Ws = (__half*)sm;                     // [32][SW]
    __half* As = (__half*)sm + 32 * SW;           // [2][128][SA]

    const int tid = threadIdx.x, cta = blockIdx.x;
    const int w = tid >> 5, lane = tid & 31, gq = lane >> 2, tg = lane & 3;

    // resident weight slice
    {
        const uint4* src = (const uint4*)(g_Wp + (size_t)cta * 32 * KK);
        const int per = KK / 8;     // 192
        for (int i = tid; i < 32 * per; i += 256) {
            int r = i / per, c = i % per;
            *(uint4*)(Ws + r * SW + c * 8) = src[(size_t)r * per + c];
        }
    }
    float bias[4][2];
    {
        int j = cta * 8 + tg * 2;
        bias[0][0] = bf[j]; bias[0][1] = bf[j + 1];
        bias[1][0] = bi[j]; bias[1][1] = bi[j + 1];
        bias[2][0] = bo[j]; bias[2][1] = bo[j + 1];
        bias[3][0] = bc[j]; bias[3][1] = bc[j + 1];
    }
    unsigned base_phase = *(volatile unsigned*)&g_phase;
    __syncthreads();

    const int ltid = tid & 127;     // staging lane id for warps 4-7

    for (int t = 0; t < TT; ++t) {
        const __half* hcur  = g_h[t & 1];
        __half*       hnxt  = g_h[(t & 1) ^ 1];
        const __half* ubase = g_u16 + (size_t)t * BB * NIN;

        // prologue: warps 4-7 stage chunk 0 into buffer 0
        if (w >= 4) {
            __half* dst = As;                                   // buf 0
            const __half* src = hcur;                           // kc=0 < HH
            #pragma unroll
            for (int q = 0; q < 8; ++q) {
                int row = q * 16 + (ltid >> 3), c8 = ltid & 7;
                *(uint4*)(dst + row * SA + c8 * 8) =
                    *(const uint4*)(src + (size_t)row * HH + c8 * 8);
            }
        }
        __syncthreads();

        float acc[2][4][4];
        #pragma unroll
        for (int mt = 0; mt < 2; ++mt)
            #pragma unroll
            for (int nt = 0; nt < 4; ++nt)
                #pragma unroll
                for (int e = 0; e < 4; ++e) acc[mt][nt][e] = 0.0f;

        for (int i = 0; i < KK / KC; ++i) {
            if (w >= 4) {
                if (i + 1 < KK / KC) {
                    int kc = (i + 1) * KC;
                    __half* dst = As + ((i + 1) & 1) * BB * SA;
                    const __half* src; int stride;
                    if (kc < HH) { src = hcur + kc;           stride = HH;  }
                    else         { src = ubase + (kc - HH);   stride = NIN; }
                    #pragma unroll
                    for (int q = 0; q < 8; ++q) {
                        int row = q * 16 + (ltid >> 3), c8 = ltid & 7;
                        *(uint4*)(dst + row * SA + c8 * 8) =
                            *(const uint4*)(src + (size_t)row * stride + c8 * 8);
                    }
                }
            } else {
                const __half* A0 = As + (i & 1) * BB * SA;
                const int kc = i * KC;
                #pragma unroll
                for (int ks = 0; ks < KC; ks += 16) {
                    unsigned a[2][4];
                    #pragma unroll
                    for (int mt = 0; mt < 2; ++mt) {
                        const __half* Ap = A0 + (w * 32 + mt * 16 + gq) * SA + ks + tg * 2;
                        a[mt][0] = *(const unsigned*)(Ap);
                        a[mt][1] = *(const unsigned*)(Ap + 8 * SA);
                        a[mt][2] = *(const unsigned*)(Ap + 8);
                        a[mt][3] = *(const unsigned*)(Ap + 8 * SA + 8);
                    }
                    #pragma unroll
                    for (int nt = 0; nt < 4; ++nt) {
                        const __half* Bp = Ws + (nt * 8 + gq) * SW + kc + ks + tg * 2;
                        unsigned b0 = *(const unsigned*)(Bp);
                        unsigned b1 = *(const unsigned*)(Bp + 8);
                        mma16816(acc[0][nt], a[0], b0, b1);
                        mma16816(acc[1][nt], a[1], b0, b1);
                    }
                }
            }
            __syncthreads();
        }

        // gates (warps 0-3; the 4 n-tiles are exactly the 4 gates)
        if (w < 4) {
            const int j0 = cta * 8 + tg * 2;
            #pragma unroll
            for (int mt = 0; mt < 2; ++mt) {
                #pragma unroll
                for (int rr = 0; rr < 2; ++rr) {
                    int R = w * 32 + mt * 16 + gq + rr * 8;
                    __half2 h2 = *(const __half2*)(hcur + (size_t)R * HH + j0);
                    float hold[2] = { __low2float(h2), __high2float(h2) };
                    float hn[2];
                    #pragma unroll
                    for (int c = 0; c < 2; ++c) {
                        int e = rr * 2 + c;
                        float f  = sigmoidf_(acc[mt][0][e] + bias[0][c]);
                        float ii = sigmoidf_(acc[mt][1][e] + bias[1][c]);
                        float o  = sigmoidf_(acc[mt][2][e] + bias[2][c]);
                        float ct = tanhf(acc[mt][3][e] + bias[3][c]);
                        float cn = f * hold[c] + ii * ct;      // faithful: uses h
                        hn[c] = o * tanhf(cn);
                    }
                    __half2 hv = __floats2half2_rn(hn[0], hn[1]);
                    *(__half2*)(hnxt + (size_t)R * HH + j0) = hv;
                    *(__half2*)(g_hist + (size_t)t * BB * HH + (size_t)R * HH + j0) = hv;
                }
            }
        }
        __syncthreads();

        // grid barrier (epoch-based; wrap-safe; replay-safe)
        if (tid == 0) {
            __threadfence();
            unsigned target = base_phase + (unsigned)(t + 1);
            if (atomicAdd(&g_cnt, 1u) == NCTA - 1) {
                atomicExch(&g_cnt, 0u);
                __threadfence();
                atomicExch(&g_phase, target);
            } else {
                while ((int)(*(volatile unsigned*)&g_phase - target) < 0) __nanosleep(32);
            }
            __threadfence();
        }
        __syncthreads();
    }
}

// ---------------- output pass: y = softmax(hist @ Wy + by) ----------------
__global__ void __launch_bounds__(256, 1)
y_kernel(const float* __restrict__ by, float* __restrict__ out)
{
    extern __shared__ char sm[];
    __half* As = (__half*)sm;                 // [128][SAY]
    __half* Bs = (__half*)sm + BB * SAY;      // [256][SAY]

    const int tid = threadIdx.x, w = tid >> 5, lane = tid & 31;
    const int gq = lane >> 2, tg = lane & 3;
    const int t = blockIdx.x;
    const size_t rowbase = (size_t)t * BB;
    const int R1 = w * 16 + gq;

    float acc[32][4];
    #pragma unroll
    for (int nt = 0; nt < 32; ++nt)
        #pragma unroll
        for (int e = 0; e < 4; ++e) acc[nt][e] = 0.0f;

    for (int kc = 0; kc < HH; kc += 64) {
        #pragma unroll
        for (int p = 0; p < 4; ++p) {
            int row = p * 32 + (tid >> 3), c8 = tid & 7;
            *(uint4*)(As + row * SAY + c8 * 8) =
                *(const uint4*)(g_hist + (rowbase + row) * HH + kc + c8 * 8);
        }
        #pragma unroll
        for (int p = 0; p < 8; ++p) {
            int row = p * 32 + (tid >> 3), c8 = tid & 7;
            *(uint4*)(Bs + row * SAY + c8 * 8) =
                *(const uint4*)(g_Wy + (size_t)row * HH + kc + c8 * 8);
        }
        __syncthreads();
        #pragma unroll
        for (int ks = 0; ks < 64; ks += 16) {
            const __half* Ap = As + R1 * SAY + ks + tg * 2;
            unsigned a[4];
            a[0] = *(const unsigned*)(Ap);
            a[1] = *(const unsigned*)(Ap + 8 * SAY);
            a[2] = *(const unsigned*)(Ap + 8);
            a[3] = *(const unsigned*)(Ap + 8 * SAY + 8);
            #pragma unroll
            for (int nt = 0; nt < 32; ++nt) {
                const __half* Bp = Bs + (nt * 8 + gq) * SAY + ks + tg * 2;
                mma16816(acc[nt], a, *(const unsigned*)(Bp), *(const unsigned*)(Bp + 8));
            }
        }
        __syncthreads();
    }

    // softmax over 256 cols; each row's cols live in a 4-lane quad (xor 1,2)
    #pragma unroll
    for (int rr = 0; rr < 2; ++rr) {
        float m = -1e30f;
        #pragma unroll
        for (int nt = 0; nt < 32; ++nt)
            #pragma unroll
            for (int c = 0; c < 2; ++c) {
                float v = acc[nt][rr * 2 + c] + __ldg(&by[nt * 8 + tg * 2 + c]);
                acc[nt][rr * 2 + c] = v;
                m = fmaxf(m, v);
            }
        m = fmaxf(m, __shfl_xor_sync(0xffffffffu, m, 1));
        m = fmaxf(m, __shfl_xor_sync(0xffffffffu, m, 2));
        float s = 0.0f;
        #pragma unroll
        for (int nt = 0; nt < 32; ++nt)
            #pragma unroll
            for (int c = 0; c < 2; ++c) {
                float e = __expf(acc[nt][rr * 2 + c] - m);
                acc[nt][rr * 2 + c] = e;
                s += e;
            }
        s += __shfl_xor_sync(0xffffffffu, s, 1);
        s += __shfl_xor_sync(0xffffffffu, s, 2);
        float inv = 1.0f / s;
        int b = R1 + rr * 8;
        float* orow = out + ((size_t)b * TT + t) * NOUT;
        #pragma unroll
        for (int nt = 0; nt < 32; ++nt) {
            float2 pr = make_float2(acc[nt][rr * 2] * inv, acc[nt][rr * 2 + 1] * inv);
            *(float2*)(orow + nt * 8 + tg * 2) = pr;
        }
    }
}

// ---------------- launcher ----------------
extern "C" void kernel_launch(void* const* d_in, const int* in_sizes, int n_in,
                              void* d_out, int out_size)
{
    const float* u   = (const float*)d_in[0];
    const float* Wuf = (const float*)d_in[1];
    const float* Wui = (const float*)d_in[2];
    const float* Wuo = (const float*)d_in[3];
    const float* Wuc = (const float*)d_in[4];
    const float* Whf = (const float*)d_in[5];
    const float* Whi = (const float*)d_in[6];
    const float* Who = (const float*)d_in[7];
    const float* Whc = (const float*)d_in[8];
    const float* Why = (const float*)d_in[9];
    const float* bf  = (const float*)d_in[10];
    const float* bi  = (const float*)d_in[11];
    const float* bo  = (const float*)d_in[12];
    const float* bc  = (const float*)d_in[13];
    const float* by  = (const float*)d_in[14];
    const float* h0  = (const float*)d_in[15];
    // d_in[16] = c0 (dead in this recurrence)
    float* out = (float*)d_out;

    cudaFuncSetAttribute(lstm_main, cudaFuncAttributeMaxDynamicSharedMemorySize, SMEM_MAIN);
    cudaFuncSetAttribute(y_kernel,  cudaFuncAttributeMaxDynamicSharedMemorySize, SMEM_Y);

    pack_w_kernel<<<dim3(32, 48, 4), dim3(32, 8)>>>(Whf, Whi, Who, Whc, Wuf, Wui, Wuo, Wuc);
    pack_u_kernel<<<(BB * TT * NIN) / 256, 256>>>(u);
    pack_misc_kernel<<<(NOUT * HH) / 256, 256>>>(Why, h0);
    lstm_main<<<NCTA, 256, SMEM_MAIN>>>(bf, bi, bo, bc);
    y_kernel<<<TT, 256, SMEM_Y>>>(by, out);
}

// round 5
// speedup vs baseline: 1.0516x; 1.0516x over previous
#include <cuda_runtime.h>
#include <cuda_fp16.h>

#define BB   128
#define TT   1024
#define NIN  512
#define HH   1024
#define NOUT 256
#define KK   1536
#define NCTA 128

#define SW     1544                 // W smem row stride (halves), conflict-free
#define WBYTES (32 * SW * 2)        // 98816
#define NST    6                    // ring slots
#define NCHUNK 24                   // 24 chunks x 64 k per step (8 u + 16 h)
#define STB    18432                // stage bytes: 128 rows x 72 halves x 2
#define A_OFF  WBYTES
#define BAR_OFF (A_OFF + NST * STB) // 209408; full[s]=+s*16, empty[s]=+s*16+8
#define SMEM_MAIN (BAR_OFF + 128)   // 209536

#define SAY 72
#define SMEM_Y ((BB + NOUT) * SAY * 2)

// ---------------- device scratch ----------------
__device__ __half  g_Wp[(size_t)NCTA * 32 * KK];     // [cta][l=32][k=1536] fp16 (k: h then u)
__device__ __half  g_u16[(size_t)TT * BB * NIN];     // [t][b][n] fp16
__device__ __half  g_h[2][BB * HH];                  // double-buffered hidden
__device__ __half  g_hist[(size_t)TT * BB * HH];     // h history
__device__ __half  g_Wy[(size_t)NOUT * HH];          // W_hy^T [n][k]
__device__ unsigned g_cnt;
__device__ unsigned g_phase;

// ---------------- ptx helpers ----------------
__device__ __forceinline__ unsigned smem_u32(const void* p) {
    unsigned a;
    asm("{ .reg .u64 t; cvta.to.shared.u64 t, %1; cvt.u32.u64 %0, t; }" : "=r"(a) : "l"(p));
    return a;
}
#define MBARRIER_INIT(addr, cnt) \
    asm volatile("mbarrier.init.shared.b64 [%0], %1;" :: "r"((unsigned)(addr)), "r"((unsigned)(cnt)) : "memory")
#define MBARRIER_ARRIVE(addr) \
    asm volatile("mbarrier.arrive.shared.b64 _, [%0];" :: "r"((unsigned)(addr)) : "memory")
#define MBARRIER_WAIT_PARITY(addr, par) do {                                   \
    unsigned _m = (unsigned)(addr), _p = (unsigned)(par), _d;                  \
    asm volatile("{\n\t.reg .pred p;\n\t"                                      \
        "mbarrier.try_wait.parity.acquire.cta.shared::cta.b64 p, [%1], %2;\n\t"\
        "selp.b32 %0, 1, 0, p;\n\t}" : "=r"(_d) : "r"(_m), "r"(_p) : "memory");\
    if (!_d) {                                                                 \
        asm volatile("{\n\t.reg .pred P1;\n\t"                                 \
            "W%=:\n\t"                                                         \
            "mbarrier.try_wait.parity.acquire.cta.shared::cta.b64 P1, [%0], %1, 0x989680;\n\t"\
            "@P1 bra.uni D%=;\n\t"                                             \
            "bra.uni W%=;\n\t"                                                 \
            "D%=:\n\t}" :: "r"(_m), "r"(_p) : "memory");                       \
    }                                                                          \
} while (0)
#define CPA16(dst, src) \
    asm volatile("cp.async.cg.shared.global [%0], [%1], 16;" :: "r"((unsigned)(dst)), "l"(src) : "memory")
#define CPA_ARRIVE(mb) \
    asm volatile("cp.async.mbarrier.arrive.noinc.shared.b64 [%0];" :: "r"((unsigned)(mb)) : "memory")

__device__ __forceinline__ void mma16816(float* c, const unsigned* a, unsigned b0, unsigned b1) {
    asm volatile(
        "mma.sync.aligned.m16n8k16.row.col.f32.f16.f16.f32 "
        "{%0,%1,%2,%3}, {%4,%5,%6,%7}, {%8,%9}, {%0,%1,%2,%3};"
        : "+f"(c[0]), "+f"(c[1]), "+f"(c[2]), "+f"(c[3])
        : "r"(a[0]), "r"(a[1]), "r"(a[2]), "r"(a[3]), "r"(b0), "r"(b1));
}
__device__ __forceinline__ float sigmoidf_(float x) { return 1.0f / (1.0f + __expf(-x)); }

// ---------------- prep ----------------
__global__ void pack_w_kernel(const float* __restrict__ Whf, const float* __restrict__ Whi,
                              const float* __restrict__ Who, const float* __restrict__ Whc,
                              const float* __restrict__ Wuf, const float* __restrict__ Wui,
                              const float* __restrict__ Wuo, const float* __restrict__ Wuc)
{
    __shared__ float tile[32][33];
    int jt = blockIdx.x;            // j tile
    int kt = blockIdx.y;            // k tile
    int g  = blockIdx.z;            // gate
    int tx = threadIdx.x;
    int ty = threadIdx.y;
    const float* Wh = (g == 0) ? Whf : (g == 1) ? Whi : (g == 2) ? Who : Whc;
    const float* Wu = (g == 0) ? Wuf : (g == 1) ? Wui : (g == 2) ? Wuo : Wuc;
    int kbase = kt * 32;
    #pragma unroll
    for (int r = 0; r < 4; ++r) {
        int k = kbase + ty * 4 + r;
        int j = jt * 32 + tx;
        float v = (k < HH) ? Wh[(size_t)k * HH + j] : Wu[(size_t)(k - HH) * HH + j];
        tile[ty * 4 + r][tx] = v;
    }
    __syncthreads();
    #pragma unroll
    for (int r = 0; r < 4; ++r) {
        int jl = ty * 4 + r;
        int j = jt * 32 + jl;
        int row = (j >> 3) * 32 + g * 8 + (j & 7);      // cta = j>>3, l = g*8 + (j&7)
        g_Wp[(size_t)row * KK + kbase + tx] = __float2half_rn(tile[tx][jl]);
    }
}

__global__ void pack_u_kernel(const float* __restrict__ u)
{
    long long idx = (long long)blockIdx.x * blockDim.x + threadIdx.x;
    if (idx >= (long long)BB * TT * NIN) return;
    int n = (int)(idx & (NIN - 1));
    int t = (int)((idx >> 9) & (TT - 1));
    int b = (int)(idx >> 19);
    g_u16[((size_t)t * BB + b) * NIN + n] = __float2half_rn(u[idx]);
}

__global__ void pack_misc_kernel(const float* __restrict__ Why, const float* __restrict__ h0)
{
    int idx = blockIdx.x * blockDim.x + threadIdx.x;
    if (idx < NOUT * HH) {
        int n = idx / HH, k = idx % HH;
        g_Wy[idx] = __float2half_rn(Why[(size_t)k * NOUT + n]);
    }
    if (idx < BB * HH) {
        g_h[0][idx] = __float2half_rn(h0[idx & (HH - 1)]);
    }
}

// ---------------- persistent recurrent kernel ----------------
// Warps 0-3: MMA consumers (m32 n32 each). Warps 4-7: cp.async producers.
// 24 chunks/step (8 u-chunks then 16 h-chunks), 6-slot ring, mbarrier handoff.
__global__ void __launch_bounds__(256, 1)
lstm_main(const float* __restrict__ bf, const float* __restrict__ bi,
          const float* __restrict__ bo, const float* __restrict__ bc)
{
    extern __shared__ char sm[];
    __half* Ws = (__half*)sm;                     // [32][SW]
    const unsigned smb = smem_u32(sm);
    const int tid = threadIdx.x, cta = blockIdx.x;
    const int w = tid >> 5, lane = tid & 31, gq = lane >> 2, tg = lane & 3;

    // resident weight slice
    {
        const uint4* src = (const uint4*)(g_Wp + (size_t)cta * 32 * KK);
        const int per = KK / 8;     // 192
        for (int i = tid; i < 32 * per; i += 256) {
            int r = i / per, c = i % per;
            *(uint4*)(Ws + r * SW + c * 8) = src[(size_t)r * per + c];
        }
    }
    if (tid == 0) {
        #pragma unroll
        for (int s = 0; s < NST; ++s) {
            MBARRIER_INIT(smb + BAR_OFF + s * 16, 128);      // full: 128 producer arrives
            MBARRIER_INIT(smb + BAR_OFF + s * 16 + 8, 4);    // empty: 4 consumer-warp arrives
        }
    }
    float bias[4][2];
    if (w < 4) {
        int j = cta * 8 + tg * 2;
        bias[0][0] = bf[j]; bias[0][1] = bf[j + 1];
        bias[1][0] = bi[j]; bias[1][1] = bi[j + 1];
        bias[2][0] = bo[j]; bias[2][1] = bo[j + 1];
        bias[3][0] = bc[j]; bias[3][1] = bc[j + 1];
    }
    unsigned base_phase = *(volatile unsigned*)&g_phase;
    __syncthreads();

    if (w >= 4) {
        // ================= producers =================
        const int ltid    = tid - 128;          // 0..127
        const int halfsel = ltid & 1;           // 64B half of a 128B row
        const int rowb    = ltid >> 1;          // 0..63
        for (int t = 0; t < TT; ++t) {
            const __half* hcur  = g_h[t & 1];
            const __half* ubase = g_u16 + (size_t)t * BB * NIN;
            for (int c = 0; c < NCHUNK; ++c) {
                const int G = t * NCHUNK + c;
                const int s = G % NST;
                if (c == 8) {                    // first h-chunk: gate on grid phase
                    if (lane == 0) {
                        unsigned tgt = base_phase + (unsigned)t;
                        while ((int)(*(volatile unsigned*)&g_phase - tgt) < 0) __nanosleep(64);
                    }
                    __syncwarp();
                }
                if (G >= NST) {
                    unsigned par = (unsigned)(G / NST - 1) & 1u;
                    MBARRIER_WAIT_PARITY(smb + BAR_OFF + s * 16 + 8, par);
                }
                const __half* src; int stride;
                if (c < 8) { src = ubase + c * 64;       stride = NIN; }
                else       { src = hcur + (c - 8) * 64;  stride = HH;  }
                const unsigned dst0 = smb + A_OFF + s * STB;
                #pragma unroll
                for (int pass = 0; pass < 2; ++pass) {
                    int row = pass * 64 + rowb;
                    const __half* sr = src + (size_t)row * stride + halfsel * 32;
                    unsigned dr = dst0 + row * 144 + halfsel * 64;
                    CPA16(dr,      sr);
                    CPA16(dr + 16, sr + 8);
                    CPA16(dr + 32, sr + 16);
                    CPA16(dr + 48, sr + 24);
                }
                CPA_ARRIVE(smb + BAR_OFF + s * 16);
            }
        }
    } else {
        // ================= consumers =================
        for (int t = 0; t < TT; ++t) {
            const __half* hcur = g_h[t & 1];
            __half*       hnxt = g_h[(t & 1) ^ 1];

            float acc[2][4][4];
            #pragma unroll
            for (int mt = 0; mt < 2; ++mt)
                #pragma unroll
                for (int nt = 0; nt < 4; ++nt)
                    #pragma unroll
                    for (int e = 0; e < 4; ++e) acc[mt][nt][e] = 0.0f;

            for (int c = 0; c < NCHUNK; ++c) {
                const int G = t * NCHUNK + c;
                const int s = G % NST;
                MBARRIER_WAIT_PARITY(smb + BAR_OFF + s * 16, (unsigned)(G / NST) & 1u);
                const __half* Ast = (const __half*)(sm + A_OFF + s * STB);
                const int kcW = (c < 8) ? (1024 + c * 64) : ((c - 8) * 64);
                #pragma unroll
                for (int ks = 0; ks < 64; ks += 16) {
                    unsigned a[2][4];
                    #pragma unroll
                    for (int mt = 0; mt < 2; ++mt) {
                        const __half* Ap = Ast + (w * 32 + mt * 16 + gq) * 72 + ks + tg * 2;
                        a[mt][0] = *(const unsigned*)(Ap);
                        a[mt][1] = *(const unsigned*)(Ap + 8 * 72);
                        a[mt][2] = *(const unsigned*)(Ap + 8);
                        a[mt][3] = *(const unsigned*)(Ap + 8 * 72 + 8);
                    }
                    #pragma unroll
                    for (int nt = 0; nt < 4; ++nt) {
                        const __half* Bp = Ws + (nt * 8 + gq) * SW + kcW + ks + tg * 2;
                        unsigned b0 = *(const unsigned*)(Bp);
                        unsigned b1 = *(const unsigned*)(Bp + 8);
                        mma16816(acc[0][nt], a[0], b0, b1);
                        mma16816(acc[1][nt], a[1], b0, b1);
                    }
                }
                __syncwarp();
                if (lane == 0) MBARRIER_ARRIVE(smb + BAR_OFF + s * 16 + 8);
            }

            // gates (the 4 n-tiles are exactly the 4 gates)
            const int j0 = cta * 8 + tg * 2;
            #pragma unroll
            for (int mt = 0; mt < 2; ++mt) {
                #pragma unroll
                for (int rr = 0; rr < 2; ++rr) {
                    int R = w * 32 + mt * 16 + gq + rr * 8;
                    __half2 h2 = *(const __half2*)(hcur + (size_t)R * HH + j0);
                    float hold[2] = { __low2float(h2), __high2float(h2) };
                    float hn[2];
                    #pragma unroll
                    for (int cc = 0; cc < 2; ++cc) {
                        int e = rr * 2 + cc;
                        float f  = sigmoidf_(acc[mt][0][e] + bias[0][cc]);
                        float ii = sigmoidf_(acc[mt][1][e] + bias[1][cc]);
                        float o  = sigmoidf_(acc[mt][2][e] + bias[2][cc]);
                        float ct = tanhf(acc[mt][3][e] + bias[3][cc]);
                        float cn = f * hold[cc] + ii * ct;      // faithful: uses h
                        hn[cc] = o * tanhf(cn);
                    }
                    __half2 hv = __floats2half2_rn(hn[0], hn[1]);
                    *(__half2*)(hnxt + (size_t)R * HH + j0) = hv;
                    *(__half2*)(g_hist + ((size_t)t * BB + R) * HH + j0) = hv;
                }
            }

            // release grid phase (consumers only; producers poll it)
            asm volatile("bar.sync 1, 128;" ::: "memory");
            if (tid == 0) {
                __threadfence();
                unsigned target = base_phase + (unsigned)(t + 1);
                if (atomicAdd(&g_cnt, 1u) == NCTA - 1) {
                    atomicExch(&g_cnt, 0u);
                    __threadfence();
                    atomicExch(&g_phase, target);
                }
            }
        }
    }
}

// ---------------- output pass: y = softmax(hist @ Wy + by) ----------------
__global__ void __launch_bounds__(256, 1)
y_kernel(const float* __restrict__ by, float* __restrict__ out)
{
    extern __shared__ char sm[];
    __half* As = (__half*)sm;
    __half* Bs = (__half*)sm + BB * SAY;

    const int tid = threadIdx.x, w = tid >> 5, lane = tid & 31;
    const int gq = lane >> 2, tg = lane & 3;
    const int t = blockIdx.x;
    const size_t rowbase = (size_t)t * BB;
    const int R1 = w * 16 + gq;

    float acc[32][4];
    #pragma unroll
    for (int nt = 0; nt < 32; ++nt)
        #pragma unroll
        for (int e = 0; e < 4; ++e) acc[nt][e] = 0.0f;

    for (int kc = 0; kc < HH; kc += 64) {
        #pragma unroll
        for (int p = 0; p < 4; ++p) {
            int row = p * 32 + (tid >> 3), c8 = tid & 7;
            *(uint4*)(As + row * SAY + c8 * 8) =
                *(const uint4*)(g_hist + (rowbase + row) * HH + kc + c8 * 8);
        }
        #pragma unroll
        for (int p = 0; p < 8; ++p) {
            int row = p * 32 + (tid >> 3), c8 = tid & 7;
            *(uint4*)(Bs + row * SAY + c8 * 8) =
                *(const uint4*)(g_Wy + (size_t)row * HH + kc + c8 * 8);
        }
        __syncthreads();
        #pragma unroll
        for (int ks = 0; ks < 64; ks += 16) {
            const __half* Ap = As + R1 * SAY + ks + tg * 2;
            unsigned a[4];
            a[0] = *(const unsigned*)(Ap);
            a[1] = *(const unsigned*)(Ap + 8 * SAY);
            a[2] = *(const unsigned*)(Ap + 8);
            a[3] = *(const unsigned*)(Ap + 8 * SAY + 8);
            #pragma unroll
            for (int nt = 0; nt < 32; ++nt) {
                const __half* Bp = Bs + (nt * 8 + gq) * SAY + ks + tg * 2;
                mma16816(acc[nt], a, *(const unsigned*)(Bp), *(const unsigned*)(Bp + 8));
            }
        }
        __syncthreads();
    }

    #pragma unroll
    for (int rr = 0; rr < 2; ++rr) {
        float m = -1e30f;
        #pragma unroll
        for (int nt = 0; nt < 32; ++nt)
            #pragma unroll
            for (int c = 0; c < 2; ++c) {
                float v = acc[nt][rr * 2 + c] + __ldg(&by[nt * 8 + tg * 2 + c]);
                acc[nt][rr * 2 + c] = v;
                m = fmaxf(m, v);
            }
        m = fmaxf(m, __shfl_xor_sync(0xffffffffu, m, 1));
        m = fmaxf(m, __shfl_xor_sync(0xffffffffu, m, 2));
        float s = 0.0f;
        #pragma unroll
        for (int nt = 0; nt < 32; ++nt)
            #pragma unroll
            for (int c = 0; c < 2; ++c) {
                float e = __expf(acc[nt][rr * 2 + c] - m);
                acc[nt][rr * 2 + c] = e;
                s += e;
            }
        s += __shfl_xor_sync(0xffffffffu, s, 1);
        s += __shfl_xor_sync(0xffffffffu, s, 2);
        float inv = 1.0f / s;
        int b = R1 + rr * 8;
        float* orow = out + ((size_t)b * TT + t) * NOUT;
        #pragma unroll
        for (int nt = 0; nt < 32; ++nt) {
            float2 pr = make_float2(acc[nt][rr * 2] * inv, acc[nt][rr * 2 + 1] * inv);
            *(float2*)(orow + nt * 8 + tg * 2) = pr;
        }
    }
}

// ---------------- launcher ----------------
extern "C" void kernel_launch(void* const* d_in, const int* in_sizes, int n_in,
                              void* d_out, int out_size)
{
    const float* u   = (const float*)d_in[0];
    const float* Wuf = (const float*)d_in[1];
    const float* Wui = (const float*)d_in[2];
    const float* Wuo = (const float*)d_in[3];
    const float* Wuc = (const float*)d_in[4];
    const float* Whf = (const float*)d_in[5];
    const float* Whi = (const float*)d_in[6];
    const float* Who = (const float*)d_in[7];
    const float* Whc = (const float*)d_in[8];
    const float* Why = (const float*)d_in[9];
    const float* bf  = (const float*)d_in[10];
    const float* bi  = (const float*)d_in[11];
    const float* bo  = (const float*)d_in[12];
    const float* bc  = (const float*)d_in[13];
    const float* by  = (const float*)d_in[14];
    const float* h0  = (const float*)d_in[15];
    float* out = (float*)d_out;

    cudaFuncSetAttribute(lstm_main, cudaFuncAttributeMaxDynamicSharedMemorySize, SMEM_MAIN);
    cudaFuncSetAttribute(y_kernel,  cudaFuncAttributeMaxDynamicSharedMemorySize, SMEM_Y);

    pack_w_kernel<<<dim3(32, 48, 4), dim3(32, 8)>>>(Whf, Whi, Who, Whc, Wuf, Wui, Wuo, Wuc);
    pack_u_kernel<<<(BB * TT * NIN) / 256, 256>>>(u);
    pack_misc_kernel<<<(NOUT * HH) / 256, 256>>>(Why, h0);
    lstm_main<<<NCTA, 256, SMEM_MAIN>>>(bf, bi, bo, bc);
    y_kernel<<<TT, 256, SMEM_Y>>>(by, out);
}

// round 7
// speedup vs baseline: 1.1456x; 1.0894x over previous
#include <cuda_runtime.h>
#include <cuda_fp16.h>

#define BB   128
#define TT   1024
#define NIN  512
#define HH   1024
#define NOUT 256
#define NG   4096
#define NCTA 128

// ---- main kernel SMEM layout ----
#define WSTRIDE 1032                      // halves; 2064B rows = 129 x 16B (LDSM conflict-free)
#define WBYTES  (32 * WSTRIDE * 2)        // 66048
#define NST     6
#define NCHUNK  16                        // 16 h-chunks x 64 k
#define STB     (128 * 144)               // 18432 (144B rows = 9 x 16B)
#define A_OFF   WBYTES
#define XTB     (32 * 132 * 4)            // 16896 (132-float rows, 528B = 33 x 16B)
#define X_OFF   (A_OFF + NST * STB)       // 176640
#define BAR_OFF (X_OFF + 2 * XTB)         // 210432
#define SMEM_MAIN (BAR_OFF + 128)         // 210560

#define SAY 72
#define SMEM_Y ((BB + NOUT) * SAY * 2)
#define XG_SMEM (2 * 128 * 72 * 2)        // 36864

// ---------------- device scratch ----------------
__device__ __half  g_Wp [(size_t)NCTA * 32 * HH];    // recurrent W  [cta][l=32][k=1024]
__device__ __half  g_WuT[(size_t)NG * NIN];          // input W^T    [l=4096][k=512]
__device__ __half  g_u16[(size_t)TT * BB * NIN];     // [t][b][n]
__device__ __half  g_h[2][BB * HH];                  // double-buffered hidden
__device__ __half  g_hist[(size_t)TT * BB * HH];     // h history
__device__ __half  g_Wy [(size_t)NOUT * HH];         // W_hy^T [n][k]
__device__ float   g_X  [(size_t)TT * NG * BB];      // precomputed gate pre-acts (+bias)
__device__ unsigned g_l1[16];                        // tree barrier leaves (monotonic)
__device__ unsigned g_root;                          // tree barrier root  (monotonic)
__device__ unsigned g_phase;                         // epoch (monotonic)

// ---------------- ptx helpers ----------------
__device__ __forceinline__ unsigned smem_u32(const void* p) {
    unsigned a;
    asm("{ .reg .u64 t; cvta.to.shared.u64 t, %1; cvt.u32.u64 %0, t; }" : "=r"(a) : "l"(p));
    return a;
}
#define MBARRIER_INIT(addr, cnt) \
    asm volatile("mbarrier.init.shared.b64 [%0], %1;" :: "r"((unsigned)(addr)), "r"((unsigned)(cnt)) : "memory")
#define MBARRIER_ARRIVE(addr) \
    asm volatile("mbarrier.arrive.shared.b64 _, [%0];" :: "r"((unsigned)(addr)) : "memory")
#define MBARRIER_WAIT_PARITY(addr, par) do {                                   \
    unsigned _m = (unsigned)(addr), _p = (unsigned)(par), _d;                  \
    asm volatile("{\n\t.reg .pred p;\n\t"                                      \
        "mbarrier.try_wait.parity.acquire.cta.shared::cta.b64 p, [%1], %2;\n\t"\
        "selp.b32 %0, 1, 0, p;\n\t}" : "=r"(_d) : "r"(_m), "r"(_p) : "memory");\
    if (!_d) {                                                                 \
        asm volatile("{\n\t.reg .pred P1;\n\t"                                 \
            "W%=:\n\t"                                                         \
            "mbarrier.try_wait.parity.acquire.cta.shared::cta.b64 P1, [%0], %1, 0x989680;\n\t"\
            "@P1 bra.uni D%=;\n\t"                                             \
            "bra.uni W%=;\n\t"                                                 \
            "D%=:\n\t}" :: "r"(_m), "r"(_p) : "memory");                       \
    }                                                                          \
} while (0)
#define CPA16(dst, src) \
    asm volatile("cp.async.cg.shared.global [%0], [%1], 16;" :: "r"((unsigned)(dst)), "l"(src) : "memory")
#define CPA_ARRIVE(mb) \
    asm volatile("cp.async.mbarrier.arrive.noinc.shared.b64 [%0];" :: "r"((unsigned)(mb)) : "memory")
#define LDSM4(r0, r1, r2, r3, a) \
    asm volatile("ldmatrix.sync.aligned.m8n8.x4.shared.b16 {%0,%1,%2,%3}, [%4];" \
                 : "=r"(r0), "=r"(r1), "=r"(r2), "=r"(r3) : "r"((unsigned)(a)))

__device__ __forceinline__ void mma16816(float* c, unsigned a0, unsigned a1, unsigned a2, unsigned a3,
                                         unsigned b0, unsigned b1) {
    asm volatile(
        "mma.sync.aligned.m16n8k16.row.col.f32.f16.f16.f32 "
        "{%0,%1,%2,%3}, {%4,%5,%6,%7}, {%8,%9}, {%0,%1,%2,%3};"
        : "+f"(c[0]), "+f"(c[1]), "+f"(c[2]), "+f"(c[3])
        : "r"(a0), "r"(a1), "r"(a2), "r"(a3), "r"(b0), "r"(b1));
}
__device__ __forceinline__ float sigmoidf_(float x) { return 1.0f / (1.0f + __expf(-x)); }

// ---------------- prep ----------------
__global__ void pack_wh_kernel(const float* __restrict__ Whf, const float* __restrict__ Whi,
                               const float* __restrict__ Who, const float* __restrict__ Whc)
{
    int idx = blockIdx.x * blockDim.x + threadIdx.x;     // over NCTA*32*1024
    if (idx >= NCTA * 32 * HH) return;
    int k = idx & (HH - 1);
    int l = (idx >> 10) & 31;
    int cta = idx >> 15;
    int g = (l >> 3) & 3;
    int j = cta * 8 + (l & 7);
    const float* W = (g == 0) ? Whf : (g == 1) ? Whi : (g == 2) ? Who : Whc;
    g_Wp[idx] = __float2half_rn(W[(size_t)k * HH + j]);
}

__global__ void pack_wut_kernel(const float* __restrict__ Wuf, const float* __restrict__ Wui,
                                const float* __restrict__ Wuo, const float* __restrict__ Wuc)
{
    int idx = blockIdx.x * blockDim.x + threadIdx.x;     // over 4096*512
    if (idx >= NG * NIN) return;
    int k = idx & (NIN - 1);
    int l = idx >> 9;
    int g = (l >> 3) & 3;
    int j = (l >> 5) * 8 + (l & 7);
    const float* W = (g == 0) ? Wuf : (g == 1) ? Wui : (g == 2) ? Wuo : Wuc;
    g_WuT[idx] = __float2half_rn(W[(size_t)k * HH + j]);
}

__global__ void pack_u_kernel(const float* __restrict__ u)
{
    long long idx = (long long)blockIdx.x * blockDim.x + threadIdx.x;
    if (idx >= (long long)BB * TT * NIN) return;
    int n = (int)(idx & (NIN - 1));
    int t = (int)((idx >> 9) & (TT - 1));
    int b = (int)(idx >> 19);
    g_u16[((size_t)t * BB + b) * NIN + n] = __float2half_rn(u[idx]);
}

__global__ void pack_misc_kernel(const float* __restrict__ Why, const float* __restrict__ h0)
{
    int idx = blockIdx.x * blockDim.x + threadIdx.x;
    if (idx < NOUT * HH) {
        int n = idx / HH, k = idx % HH;
        g_Wy[idx] = __float2half_rn(Why[(size_t)k * NOUT + n]);
    }
    if (idx < BB * HH) {
        g_h[0][idx] = __float2half_rn(h0[idx & (HH - 1)]);
    }
}

// ---------------- X GEMM: X[t][l][b] = sum_k WuT[l][k]*u[t][b][k] + bias[l] ----------------
__global__ void __launch_bounds__(256, 2)
xgemm_kernel(const float* __restrict__ bf, const float* __restrict__ bi,
             const float* __restrict__ bo, const float* __restrict__ bc)
{
    extern __shared__ char sm[];
    __half* As = (__half*)sm;                 // [128 l][72]
    __half* Bs = (__half*)sm + 128 * 72;      // [128 b][72]
    const unsigned asb = smem_u32(As), bsb = smem_u32(Bs);

    const int tid = threadIdx.x, w = tid >> 5, lane = tid & 31;
    const int gq = lane >> 2, tg = lane & 3;
    const int bx = blockIdx.x, t = blockIdx.y;
    const int i8 = lane & 7, sel = lane >> 3;
    const unsigned aLane = ((w * 16 + (lane & 15)) * 144) + ((lane >> 4) * 16);
    const unsigned bRowOff = ((((sel >> 1) & 1) * 8 + i8) * 144) + ((sel & 1) * 16);

    float acc[16][4];
    #pragma unroll
    for (int nt = 0; nt < 16; ++nt)
        #pragma unroll
        for (int e = 0; e < 4; ++e) acc[nt][e] = 0.0f;

    for (int kc = 0; kc < NIN; kc += 64) {
        #pragma unroll
        for (int p = 0; p < 4; ++p) {
            int row = p * 32 + (tid >> 3), c8 = tid & 7;
            *(uint4*)(As + row * 72 + c8 * 8) =
                *(const uint4*)(g_WuT + (size_t)(bx * 128 + row) * NIN + kc + c8 * 8);
            *(uint4*)(Bs + row * 72 + c8 * 8) =
                *(const uint4*)(g_u16 + ((size_t)t * BB + row) * NIN + kc + c8 * 8);
        }
        __syncthreads();
        #pragma unroll
        for (int ks = 0; ks < 4; ++ks) {
            unsigned a0, a1, a2, a3;
            LDSM4(a0, a1, a2, a3, asb + aLane + ks * 32);
            #pragma unroll
            for (int p = 0; p < 8; ++p) {
                unsigned r0, r1, r2, r3;
                LDSM4(r0, r1, r2, r3, bsb + p * (16 * 144) + bRowOff + ks * 32);
                mma16816(acc[p * 2 + 0], a0, a1, a2, a3, r0, r1);
                mma16816(acc[p * 2 + 1], a0, a1, a2, a3, r2, r3);
            }
        }
        __syncthreads();
    }

    const float* bsel[4] = {bf, bi, bo, bc};
    #pragma unroll
    for (int rr = 0; rr < 2; ++rr) {
        int l = bx * 128 + w * 16 + gq + rr * 8;
        int g = (l >> 3) & 3;
        float bv = bsel[g][(l >> 5) * 8 + (l & 7)];
        float* orow = g_X + ((size_t)t * NG + l) * BB;
        #pragma unroll
        for (int nt = 0; nt < 16; ++nt) {
            float2 v = make_float2(acc[nt][rr * 2] + bv, acc[nt][rr * 2 + 1] + bv);
            *(float2*)(orow + nt * 8 + tg * 2) = v;
        }
    }
}

// ---------------- persistent recurrent kernel ----------------
// 384 threads: warps 0-7 consumers (m16 n32 each), warps 8-11 producers (cp.async).
__global__ void __launch_bounds__(384, 1)
lstm_main()
{
    extern __shared__ char sm[];
    const unsigned smb = smem_u32(sm);
    const int tid = threadIdx.x, cta = blockIdx.x;
    const int w = tid >> 5, lane = tid & 31;

    // resident recurrent W slice [32][1024] -> stride 1032
    {
        const uint4* src = (const uint4*)(g_Wp + (size_t)cta * 32 * HH);
        for (int i = tid; i < 32 * 128; i += 384) {
            int r = i >> 7, c = i & 127;
            *(uint4*)((__half*)sm + r * WSTRIDE + c * 8) = src[(size_t)r * 128 + c];
        }
    }
    if (tid == 0) {
        #pragma unroll
        for (int s = 0; s < NST; ++s) {
            MBARRIER_INIT(smb + BAR_OFF + s * 8, 128);        // full
            MBARRIER_INIT(smb + BAR_OFF + 48 + s * 8, 8);     // empty
        }
        MBARRIER_INIT(smb + BAR_OFF + 96, 128);               // xfull[0]
        MBARRIER_INIT(smb + BAR_OFF + 104, 128);              // xfull[1]
        MBARRIER_INIT(smb + BAR_OFF + 112, 8);                // xempty[0]
        MBARRIER_INIT(smb + BAR_OFF + 120, 8);                // xempty[1]
    }
    unsigned base_phase = *(volatile unsigned*)&g_phase;
    __syncthreads();

    if (w >= 8) {
        // ================= producers =================
        const int ltid = tid - 256;                 // 0..127
        // prologue: X[0] -> buf0
        {
            int l = ltid >> 2, q = ltid & 3;
            const float* xsrc = g_X + ((size_t)0 * NG + cta * 32 + l) * BB + q * 32;
            unsigned xd = smb + X_OFF + l * 528 + q * 128;
            #pragma unroll
            for (int i = 0; i < 8; ++i) CPA16(xd + i * 16, xsrc + i * 4);
            CPA_ARRIVE(smb + BAR_OFF + 96);
        }
        for (int t = 0; t < TT; ++t) {
            const __half* hcur = g_h[t & 1];
            // gate on grid phase (h[t] fully written by all CTAs)
            if (lane == 0) {
                unsigned tgt = base_phase + (unsigned)t;
                while ((int)(*(volatile unsigned*)&g_phase - tgt) < 0) { }
            }
            __syncwarp();
            for (int c = 0; c < NCHUNK; ++c) {
                const int G = t * NCHUNK + c;
                const int s = G % NST;
                if (G >= NST) {
                    MBARRIER_WAIT_PARITY(smb + BAR_OFF + 48 + s * 8, (unsigned)(G / NST - 1) & 1u);
                }
                const __half* src = hcur + (size_t)ltid * HH + c * 64;
                unsigned dst = smb + A_OFF + s * STB + ltid * 144;
                #pragma unroll
                for (int i = 0; i < 8; ++i) CPA16(dst + i * 16, src + i * 8);
                CPA_ARRIVE(smb + BAR_OFF + s * 8);
            }
            // prefetch X[t+1]
            if (t + 1 < TT) {
                int Gx = t + 1, bx = Gx & 1;
                if (Gx >= 2) {
                    MBARRIER_WAIT_PARITY(smb + BAR_OFF + 112 + bx * 8, (unsigned)(Gx / 2 - 1) & 1u);
                }
                int l = ltid >> 2, q = ltid & 3;
                const float* xsrc = g_X + ((size_t)Gx * NG + cta * 32 + l) * BB + q * 32;
                unsigned xd = smb + X_OFF + bx * XTB + l * 528 + q * 128;
                #pragma unroll
                for (int i = 0; i < 8; ++i) CPA16(xd + i * 16, xsrc + i * 4);
                CPA_ARRIVE(smb + BAR_OFF + 96 + bx * 8);
            }
        }
    } else {
        // ================= consumers =================
        const int gq = lane >> 2, tg = lane & 3;
        const int i8 = lane & 7, sel = lane >> 3;
        const unsigned aLane = ((w * 16 + (lane & 15)) * 144) + ((lane >> 4) * 16);
        const unsigned bRowOff = ((((sel >> 1) & 1) * 8 + i8) * (WSTRIDE * 2)) + ((sel & 1) * 16);
        const int bb0 = w * 16 + gq;
        const int j0 = cta * 8 + tg * 2;

        for (int t = 0; t < TT; ++t) {
            const __half* hcur = g_h[t & 1];
            __half*       hnxt = g_h[(t & 1) ^ 1];

            float acc[4][4];
            #pragma unroll
            for (int nt = 0; nt < 4; ++nt)
                #pragma unroll
                for (int e = 0; e < 4; ++e) acc[nt][e] = 0.0f;

            __half2 hold2[2];
            for (int c = 0; c < NCHUNK; ++c) {
                const int G = t * NCHUNK + c;
                const int s = G % NST;
                MBARRIER_WAIT_PARITY(smb + BAR_OFF + s * 8, (unsigned)(G / NST) & 1u);
                if (c == 0) {
                    // phase t passed -> h[t] globally complete; prefetch h_old for gates
                    hold2[0] = *(const __half2*)(hcur + (size_t)bb0 * HH + j0);
                    hold2[1] = *(const __half2*)(hcur + (size_t)(bb0 + 8) * HH + j0);
                }
                const unsigned abase = smb + A_OFF + s * STB + aLane;
                const unsigned kb0 = (unsigned)(c * 64) * 2;
                #pragma unroll
                for (int ks = 0; ks < 4; ++ks) {
                    unsigned a0, a1, a2, a3;
                    LDSM4(a0, a1, a2, a3, abase + ks * 32);
                    unsigned kb = kb0 + ks * 32;
                    #pragma unroll
                    for (int p = 0; p < 2; ++p) {
                        unsigned r0, r1, r2, r3;
                        LDSM4(r0, r1, r2, r3, smb + p * (16 * WSTRIDE * 2) + bRowOff + kb);
                        mma16816(acc[p * 2 + 0], a0, a1, a2, a3, r0, r1);
                        mma16816(acc[p * 2 + 1], a0, a1, a2, a3, r2, r3);
                    }
                }
                __syncwarp();
                if (lane == 0) MBARRIER_ARRIVE(smb + BAR_OFF + 48 + s * 8);
            }

            // epilogue: X + gates
            MBARRIER_WAIT_PARITY(smb + BAR_OFF + 96 + (t & 1) * 8, (unsigned)(t >> 1) & 1u);
            const float* Xs = (const float*)(sm + X_OFF + (t & 1) * XTB);
            #pragma unroll
            for (int rr = 0; rr < 2; ++rr) {
                int xcol = bb0 + rr * 8;
                float hold[2] = { __low2float(hold2[rr]), __high2float(hold2[rr]) };
                float hn[2];
                #pragma unroll
                for (int cc = 0; cc < 2; ++cc) {
                    int e = rr * 2 + cc;
                    int lrow = tg * 2 + cc;
                    float f  = sigmoidf_(acc[0][e] + Xs[(0  + lrow) * 132 + xcol]);
                    float ii = sigmoidf_(acc[1][e] + Xs[(8  + lrow) * 132 + xcol]);
                    float o  = sigmoidf_(acc[2][e] + Xs[(16 + lrow) * 132 + xcol]);
                    float ct = tanhf   (acc[3][e] + Xs[(24 + lrow) * 132 + xcol]);
                    float cn = f * hold[cc] + ii * ct;    // faithful: uses h, not c
                    hn[cc] = o * tanhf(cn);
                }
                __half2 hv = __floats2half2_rn(hn[0], hn[1]);
                *(__half2*)(hnxt + (size_t)(bb0 + rr * 8) * HH + j0) = hv;
                *(__half2*)(g_hist + ((size_t)t * BB + bb0 + rr * 8) * HH + j0) = hv;
            }
            __syncwarp();
            if (lane == 0) MBARRIER_ARRIVE(smb + BAR_OFF + 112 + (t & 1) * 8);

            // release grid phase via tree barrier (consumer threads only)
            asm volatile("bar.sync 1, 256;" ::: "memory");
            if (tid == 0) {
                __threadfence();
                unsigned target = base_phase + (unsigned)(t + 1);
                unsigned v = atomicAdd(&g_l1[cta & 15], 1u);
                if ((v & 7) == 7) {
                    unsigned r = atomicAdd(&g_root, 1u);
                    if ((r & 15) == 15) {
                        __threadfence();
                        atomicExch(&g_phase, target);
                    }
                }
            }
        }
    }
}

// ---------------- output pass: y = softmax(hist @ Wy + by) ----------------
__global__ void __launch_bounds__(256, 1)
y_kernel(const float* __restrict__ by, float* __restrict__ out)
{
    extern __shared__ char sm[];
    __half* As = (__half*)sm;
    __half* Bs = (__half*)sm + BB * SAY;

    const int tid = threadIdx.x, w = tid >> 5, lane = tid & 31;
    const int gq = lane >> 2, tg = lane & 3;
    const int t = blockIdx.x;
    const size_t rowbase = (size_t)t * BB;
    const int R1 = w * 16 + gq;

    float acc[32][4];
    #pragma unroll
    for (int nt = 0; nt < 32; ++nt)
        #pragma unroll
        for (int e = 0; e < 4; ++e) acc[nt][e] = 0.0f;

    for (int kc = 0; kc < HH; kc += 64) {
        #pragma unroll
        for (int p = 0; p < 4; ++p) {
            int row = p * 32 + (tid >> 3), c8 = tid & 7;
            *(uint4*)(As + row * SAY + c8 * 8) =
                *(const uint4*)(g_hist + (rowbase + row) * HH + kc + c8 * 8);
        }
        #pragma unroll
        for (int p = 0; p < 8; ++p) {
            int row = p * 32 + (tid >> 3), c8 = tid & 7;
            *(uint4*)(Bs + row * SAY + c8 * 8) =
                *(const uint4*)(g_Wy + (size_t)row * HH + kc + c8 * 8);
        }
        __syncthreads();
        #pragma unroll
        for (int ks = 0; ks < 64; ks += 16) {
            const __half* Ap = As + R1 * SAY + ks + tg * 2;
            unsigned a0 = *(const unsigned*)(Ap);
            unsigned a1 = *(const unsigned*)(Ap + 8 * SAY);
            unsigned a2 = *(const unsigned*)(Ap + 8);
            unsigned a3 = *(const unsigned*)(Ap + 8 * SAY + 8);
            #pragma unroll
            for (int nt = 0; nt < 32; ++nt) {
                const __half* Bp = Bs + (nt * 8 + gq) * SAY + ks + tg * 2;
                mma16816(acc[nt], a0, a1, a2, a3,
                         *(const unsigned*)(Bp), *(const unsigned*)(Bp + 8));
            }
        }
        __syncthreads();
    }

    #pragma unroll
    for (int rr = 0; rr < 2; ++rr) {
        float m = -1e30f;
        #pragma unroll
        for (int nt = 0; nt < 32; ++nt)
            #pragma unroll
            for (int c = 0; c < 2; ++c) {
                float v = acc[nt][rr * 2 + c] + __ldg(&by[nt * 8 + tg * 2 + c]);
                acc[nt][rr * 2 + c] = v;
                m = fmaxf(m, v);
            }
        m = fmaxf(m, __shfl_xor_sync(0xffffffffu, m, 1));
        m = fmaxf(m, __shfl_xor_sync(0xffffffffu, m, 2));
        float s = 0.0f;
        #pragma unroll
        for (int nt = 0; nt < 32; ++nt)
            #pragma unroll
            for (int c = 0; c < 2; ++c) {
                float e = __expf(acc[nt][rr * 2 + c] - m);
                acc[nt][rr * 2 + c] = e;
                s += e;
            }
        s += __shfl_xor_sync(0xffffffffu, s, 1);
        s += __shfl_xor_sync(0xffffffffu, s, 2);
        float inv = 1.0f / s;
        int b = R1 + rr * 8;
        float* orow = out + ((size_t)b * TT + t) * NOUT;
        #pragma unroll
        for (int nt = 0; nt < 32; ++nt) {
            float2 pr = make_float2(acc[nt][rr * 2] * inv, acc[nt][rr * 2 + 1] * inv);
            *(float2*)(orow + nt * 8 + tg * 2) = pr;
        }
    }
}

// ---------------- launcher ----------------
extern "C" void kernel_launch(void* const* d_in, const int* in_sizes, int n_in,
                              void* d_out, int out_size)
{
    const float* u   = (const float*)d_in[0];
    const float* Wuf = (const float*)d_in[1];
    const float* Wui = (const float*)d_in[2];
    const float* Wuo = (const float*)d_in[3];
    const float* Wuc = (const float*)d_in[4];
    const float* Whf = (const float*)d_in[5];
    const float* Whi = (const float*)d_in[6];
    const float* Who = (const float*)d_in[7];
    const float* Whc = (const float*)d_in[8];
    const float* Why = (const float*)d_in[9];
    const float* bf  = (const float*)d_in[10];
    const float* bi  = (const float*)d_in[11];
    const float* bo  = (const float*)d_in[12];
    const float* bc  = (const float*)d_in[13];
    const float* by  = (const float*)d_in[14];
    const float* h0  = (const float*)d_in[15];
    float* out = (float*)d_out;

    cudaFuncSetAttribute(lstm_main, cudaFuncAttributeMaxDynamicSharedMemorySize, SMEM_MAIN);
    cudaFuncSetAttribute(y_kernel,  cudaFuncAttributeMaxDynamicSharedMemorySize, SMEM_Y);

    pack_wh_kernel<<<(NCTA * 32 * HH) / 256, 256>>>(Whf, Whi, Who, Whc);
    pack_wut_kernel<<<(NG * NIN) / 256, 256>>>(Wuf, Wui, Wuo, Wuc);
    pack_u_kernel<<<(BB * TT * NIN) / 256, 256>>>(u);
    pack_misc_kernel<<<(NOUT * HH) / 256, 256>>>(Why, h0);
    xgemm_kernel<<<dim3(NG / 128, TT), 256, XG_SMEM>>>(bf, bi, bo, bc);
    lstm_main<<<NCTA, 384, SMEM_MAIN>>>();
    y_kernel<<<TT, 256, SMEM_Y>>>(by, out);
}

// round 9
// speedup vs baseline: 1.2662x; 1.1053x over previous
#include <cuda_runtime.h>
#include <cuda_fp16.h>

#define BB   128
#define TT   1024
#define NIN  512
#define HH   1024
#define NOUT 256
#define NG   4096
#define NCTA 128

#define WSTRIDE 1032                      // halves; 2064B rows (129 x 16B) LDSM conflict-free
#define WBYTES  (32 * WSTRIDE * 2)        // 66048
#define NCHUNK  16

#define SAY 72
#define SMEM_Y ((BB + NOUT) * SAY * 2)
#define XG_SMEM (2 * 128 * 72 * 2)

// ---------------- device scratch ----------------
__device__ __half  g_Wp [(size_t)NCTA * 32 * HH];        // recurrent W [cta][l=32][k=1024]
__device__ __half  g_WuT[(size_t)NG * NIN];              // input W^T [l][k]
__device__ __half  g_u16[(size_t)TT * BB * NIN];         // [t][b][n]
__device__ __half  g_histx[(size_t)(TT + 1) * BB * HH];  // h[0..TT]; h[t] = step-t input
__device__ __half  g_Wy [(size_t)NOUT * HH];             // W_hy^T [n][k]
__device__ float   g_X  [(size_t)TT * NG * BB];          // u-gate pre-acts (+bias)
__device__ unsigned g_flag[(TT + 1) * 16];               // per (t, col-group) readiness 0->8

// ---------------- ptx helpers ----------------
__device__ __forceinline__ unsigned smem_u32(const void* p) {
    unsigned a;
    asm("{ .reg .u64 t; cvta.to.shared.u64 t, %1; cvt.u32.u64 %0, t; }" : "=r"(a) : "l"(p));
    return a;
}
#define LDSM4(r0, r1, r2, r3, a) \
    asm volatile("ldmatrix.sync.aligned.m8n8.x4.shared.b16 {%0,%1,%2,%3}, [%4];" \
                 : "=r"(r0), "=r"(r1), "=r"(r2), "=r"(r3) : "r"((unsigned)(a)))

__device__ __forceinline__ void mma16816(float* c, unsigned a0, unsigned a1, unsigned a2, unsigned a3,
                                         unsigned b0, unsigned b1) {
    asm volatile(
        "mma.sync.aligned.m16n8k16.row.col.f32.f16.f16.f32 "
        "{%0,%1,%2,%3}, {%4,%5,%6,%7}, {%8,%9}, {%0,%1,%2,%3};"
        : "+f"(c[0]), "+f"(c[1]), "+f"(c[2]), "+f"(c[3])
        : "r"(a0), "r"(a1), "r"(a2), "r"(a3), "r"(b0), "r"(b1));
}
__device__ __forceinline__ float tanha(float x) {
    float r; asm("tanh.approx.f32 %0, %1;" : "=f"(r) : "f"(x)); return r;
}
__device__ __forceinline__ float siga(float x) { return 0.5f * tanha(0.5f * x) + 0.5f; }

__device__ __forceinline__ void wait_flag(const unsigned* p) {
    unsigned v;
    asm volatile("ld.acquire.gpu.global.u32 %0, [%1];" : "=r"(v) : "l"(p));
    if (v < 8u) {
        do {
            __nanosleep(32);
            asm volatile("ld.acquire.gpu.global.u32 %0, [%1];" : "=r"(v) : "l"(p));
        } while (v < 8u);
    }
}
__device__ __forceinline__ void release_flag(unsigned* p) {
    asm volatile("red.release.gpu.global.add.u32 [%0], %1;" :: "l"(p), "r"(1u) : "memory");
}

// ---------------- prep ----------------
__global__ void pack_wh_kernel(const float* __restrict__ Whf, const float* __restrict__ Whi,
                               const float* __restrict__ Who, const float* __restrict__ Whc)
{
    int idx = blockIdx.x * blockDim.x + threadIdx.x;
    if (idx >= NCTA * 32 * HH) return;
    int k = idx & (HH - 1);
    int l = (idx >> 10) & 31;
    int cta = idx >> 15;
    int g = (l >> 3) & 3;
    int j = cta * 8 + (l & 7);
    const float* W = (g == 0) ? Whf : (g == 1) ? Whi : (g == 2) ? Who : Whc;
    g_Wp[idx] = __float2half_rn(W[(size_t)k * HH + j]);
}

__global__ void pack_wut_kernel(const float* __restrict__ Wuf, const float* __restrict__ Wui,
                                const float* __restrict__ Wuo, const float* __restrict__ Wuc)
{
    int idx = blockIdx.x * blockDim.x + threadIdx.x;
    if (idx >= NG * NIN) return;
    int k = idx & (NIN - 1);
    int l = idx >> 9;
    int g = (l >> 3) & 3;
    int j = (l >> 5) * 8 + (l & 7);
    const float* W = (g == 0) ? Wuf : (g == 1) ? Wui : (g == 2) ? Wuo : Wuc;
    g_WuT[idx] = __float2half_rn(W[(size_t)k * HH + j]);
}

__global__ void pack_u_kernel(const float* __restrict__ u)
{
    long long idx = (long long)blockIdx.x * blockDim.x + threadIdx.x;
    if (idx >= (long long)BB * TT * NIN) return;
    int n = (int)(idx & (NIN - 1));
    int t = (int)((idx >> 9) & (TT - 1));
    int b = (int)(idx >> 19);
    g_u16[((size_t)t * BB + b) * NIN + n] = __float2half_rn(u[idx]);
}

__global__ void pack_misc_kernel(const float* __restrict__ Why, const float* __restrict__ h0)
{
    int idx = blockIdx.x * blockDim.x + threadIdx.x;
    if (idx < NOUT * HH) {
        int n = idx / HH, k = idx % HH;
        g_Wy[idx] = __float2half_rn(Why[(size_t)k * NOUT + n]);
    }
    if (idx < BB * HH) {
        g_histx[idx] = __float2half_rn(h0[idx & (HH - 1)]);   // h[0] broadcast
    }
    if (idx < (TT + 1) * 16) {
        g_flag[idx] = (idx < 16) ? 8u : 0u;                    // h[0] ready; rest reset
    }
}

// ---------------- X GEMM: X[t][l][b] = sum_k WuT[l][k]*u[t][b][k] + bias[l] ----------------
__global__ void __launch_bounds__(256, 2)
xgemm_kernel(const float* __restrict__ bf, const float* __restrict__ bi,
             const float* __restrict__ bo, const float* __restrict__ bc)
{
    extern __shared__ char sm[];
    __half* As = (__half*)sm;                 // [128 l][72]
    __half* Bs = (__half*)sm + 128 * 72;      // [128 b][72]
    const unsigned asb = smem_u32(As), bsb = smem_u32(Bs);

    const int tid = threadIdx.x, w = tid >> 5, lane = tid & 31;
    const int gq = lane >> 2, tg = lane & 3;
    const int bx = blockIdx.x, t = blockIdx.y;
    const int i8 = lane & 7, sel = lane >> 3;
    const unsigned aLane = ((w * 16 + (lane & 15)) * 144) + ((lane >> 4) * 16);
    const unsigned bRowOff = ((((sel >> 1) & 1) * 8 + i8) * 144) + ((sel & 1) * 16);

    float acc[16][4];
    #pragma unroll
    for (int nt = 0; nt < 16; ++nt)
        #pragma unroll
        for (int e = 0; e < 4; ++e) acc[nt][e] = 0.0f;

    for (int kc = 0; kc < NIN; kc += 64) {
        #pragma unroll
        for (int p = 0; p < 4; ++p) {
            int row = p * 32 + (tid >> 3), c8 = tid & 7;
            *(uint4*)(As + row * 72 + c8 * 8) =
                *(const uint4*)(g_WuT + (size_t)(bx * 128 + row) * NIN + kc + c8 * 8);
            *(uint4*)(Bs + row * 72 + c8 * 8) =
                *(const uint4*)(g_u16 + ((size_t)t * BB + row) * NIN + kc + c8 * 8);
        }
        __syncthreads();
        #pragma unroll
        for (int ks = 0; ks < 4; ++ks) {
            unsigned a0, a1, a2, a3;
            LDSM4(a0, a1, a2, a3, asb + aLane + ks * 32);
            #pragma unroll
            for (int p = 0; p < 8; ++p) {
                unsigned r0, r1, r2, r3;
                LDSM4(r0, r1, r2, r3, bsb + p * (16 * 144) + bRowOff + ks * 32);
                mma16816(acc[p * 2 + 0], a0, a1, a2, a3, r0, r1);
                mma16816(acc[p * 2 + 1], a0, a1, a2, a3, r2, r3);
            }
        }
        __syncthreads();
    }

    const float* bsel[4] = {bf, bi, bo, bc};
    #pragma unroll
    for (int rr = 0; rr < 2; ++rr) {
        int l = bx * 128 + w * 16 + gq + rr * 8;
        int g = (l >> 3) & 3;
        float bv = bsel[g][(l >> 5) * 8 + (l & 7)];
        float* orow = g_X + ((size_t)t * NG + l) * BB;
        #pragma unroll
        for (int nt = 0; nt < 16; ++nt) {
            float2 v = make_float2(acc[nt][rr * 2] + bv, acc[nt][rr * 2 + 1] + bv);
            *(float2*)(orow + nt * 8 + tg * 2) = v;
        }
    }
}

// ---------------- persistent recurrent kernel (no global barrier) ----------------
// 256 threads = 8 MMA warps (m16 rows each). A-frags direct LDG from L2 with
// per-chunk acquire/release flags; h_old in registers; X preloaded to registers.
__global__ void __launch_bounds__(256, 1)
lstm_main(const float* __restrict__ h0)
{
    extern __shared__ char sm[];
    const unsigned smb = smem_u32(sm);
    const int tid = threadIdx.x, cta = blockIdx.x;
    const int w = tid >> 5, lane = tid & 31;
    const int gq = lane >> 2, tg = lane & 3;
    const int i8 = lane & 7, sel = lane >> 3;
    const unsigned bRowOff = ((((sel >> 1) & 1) * 8 + i8) * (WSTRIDE * 2)) + ((sel & 1) * 16);
    const int bb0 = w * 16 + gq;               // batch row (and +8)
    const int j0  = cta * 8 + tg * 2;          // hidden columns (2)
    const int c0  = cta >> 3;                  // start at own column-group's chunk

    // resident recurrent W slice [32][1024] -> stride 1032
    {
        const uint4* src = (const uint4*)(g_Wp + (size_t)cta * 32 * HH);
        for (int i = tid; i < 32 * 128; i += 256) {
            int r = i >> 7, c = i & 127;
            *(uint4*)((__half*)sm + r * WSTRIDE + c * 8) = src[(size_t)r * 128 + c];
        }
    }
    __syncthreads();

    // register-resident h_old (fp32), both rows share h0 broadcast
    float hold[2][2];
    hold[0][0] = hold[1][0] = h0[j0];
    hold[0][1] = hold[1][1] = h0[j0 + 1];

    for (int t = 0; t < TT; ++t) {
        const __half* hb = g_histx + (size_t)t * BB * HH;
        const __half* hr0 = hb + (size_t)bb0 * HH + tg * 2;
        const __half* hr8 = hr0 + 8 * HH;

        // X preload (16 scattered fp32, consumed ~5K cycles later)
        float xr[16];
        #pragma unroll
        for (int g = 0; g < 4; ++g)
            #pragma unroll
            for (int cc = 0; cc < 2; ++cc)
                #pragma unroll
                for (int rr = 0; rr < 2; ++rr)
                    xr[g * 4 + cc * 2 + rr] =
                        g_X[((size_t)t * NG + cta * 32 + g * 8 + tg * 2 + cc) * BB + bb0 + rr * 8];

        float acc[4][4];
        #pragma unroll
        for (int nt = 0; nt < 4; ++nt)
            #pragma unroll
            for (int e = 0; e < 4; ++e) acc[nt][e] = 0.0f;

        unsigned A[3][16];
        // prologue: chunks 0,1
        #pragma unroll
        for (int pi = 0; pi < 2; ++pi) {
            int c = (c0 + pi) & 15;
            wait_flag(&g_flag[t * 16 + c]);
            #pragma unroll
            for (int ks = 0; ks < 4; ++ks) {
                A[pi][ks * 4 + 0] = *(const unsigned*)(hr0 + c * 64 + ks * 16);
                A[pi][ks * 4 + 1] = *(const unsigned*)(hr8 + c * 64 + ks * 16);
                A[pi][ks * 4 + 2] = *(const unsigned*)(hr0 + c * 64 + ks * 16 + 8);
                A[pi][ks * 4 + 3] = *(const unsigned*)(hr8 + c * 64 + ks * 16 + 8);
            }
        }

        #pragma unroll
        for (int i = 0; i < NCHUNK; ++i) {
            if (i + 2 < NCHUNK) {
                int c = (c0 + i + 2) & 15;
                unsigned* Ap = A[(i + 2) % 3];
                wait_flag(&g_flag[t * 16 + c]);
                #pragma unroll
                for (int ks = 0; ks < 4; ++ks) {
                    Ap[ks * 4 + 0] = *(const unsigned*)(hr0 + c * 64 + ks * 16);
                    Ap[ks * 4 + 1] = *(const unsigned*)(hr8 + c * 64 + ks * 16);
                    Ap[ks * 4 + 2] = *(const unsigned*)(hr0 + c * 64 + ks * 16 + 8);
                    Ap[ks * 4 + 3] = *(const unsigned*)(hr8 + c * 64 + ks * 16 + 8);
                }
            }
            const unsigned* Ac = A[i % 3];
            const unsigned kb0 = (unsigned)(((c0 + i) & 15) * 128);   // bytes into W rows
            #pragma unroll
            for (int ks = 0; ks < 4; ++ks) {
                unsigned kb = kb0 + ks * 32;
                unsigned r0, r1, r2, r3;
                LDSM4(r0, r1, r2, r3, smb + bRowOff + kb);
                mma16816(acc[0], Ac[ks * 4], Ac[ks * 4 + 1], Ac[ks * 4 + 2], Ac[ks * 4 + 3], r0, r1);
                mma16816(acc[1], Ac[ks * 4], Ac[ks * 4 + 1], Ac[ks * 4 + 2], Ac[ks * 4 + 3], r2, r3);
                LDSM4(r0, r1, r2, r3, smb + 16 * (WSTRIDE * 2) + bRowOff + kb);
                mma16816(acc[2], Ac[ks * 4], Ac[ks * 4 + 1], Ac[ks * 4 + 2], Ac[ks * 4 + 3], r0, r1);
                mma16816(acc[3], Ac[ks * 4], Ac[ks * 4 + 1], Ac[ks * 4 + 2], Ac[ks * 4 + 3], r2, r3);
            }
        }

        // epilogue: gates (n-tiles are the 4 gates), register h_old, one store
        __half* hw = g_histx + (size_t)(t + 1) * BB * HH;
        #pragma unroll
        for (int rr = 0; rr < 2; ++rr) {
            float hn[2];
            #pragma unroll
            for (int cc = 0; cc < 2; ++cc) {
                int e = rr * 2 + cc;
                float f  = siga (acc[0][e] + xr[0 * 4 + cc * 2 + rr]);
                float ii = siga (acc[1][e] + xr[1 * 4 + cc * 2 + rr]);
                float o  = siga (acc[2][e] + xr[2 * 4 + cc * 2 + rr]);
                float ct = tanha(acc[3][e] + xr[3 * 4 + cc * 2 + rr]);
                float cn = f * hold[rr][cc] + ii * ct;     // faithful: uses h, not c
                hn[cc] = o * tanha(cn);
                hold[rr][cc] = hn[cc];
            }
            *(__half2*)(hw + (size_t)(bb0 + rr * 8) * HH + j0) = __floats2half2_rn(hn[0], hn[1]);
        }

        __syncthreads();                                    // all CTA stores ordered before release
        if (tid == 0) release_flag(&g_flag[(t + 1) * 16 + (cta >> 3)]);
    }
}

// ---------------- output pass: y = softmax(hist @ Wy + by) ----------------
__global__ void __launch_bounds__(256, 1)
y_kernel(const float* __restrict__ by, float* __restrict__ out)
{
    extern __shared__ char sm[];
    __half* As = (__half*)sm;
    __half* Bs = (__half*)sm + BB * SAY;

    const int tid = threadIdx.x, w = tid >> 5, lane = tid & 31;
    const int gq = lane >> 2, tg = lane & 3;
    const int t = blockIdx.x;
    const size_t rowbase = (size_t)(t + 1) * BB;            // y_t from h[t+1]
    const int R1 = w * 16 + gq;

    float acc[32][4];
    #pragma unroll
    for (int nt = 0; nt < 32; ++nt)
        #pragma unroll
        for (int e = 0; e < 4; ++e) acc[nt][e] = 0.0f;

    for (int kc = 0; kc < HH; kc += 64) {
        #pragma unroll
        for (int p = 0; p < 4; ++p) {
            int row = p * 32 + (tid >> 3), c8 = tid & 7;
            *(uint4*)(As + row * SAY + c8 * 8) =
                *(const uint4*)(g_histx + (rowbase + row) * HH + kc + c8 * 8);
        }
        #pragma unroll
        for (int p = 0; p < 8; ++p) {
            int row = p * 32 + (tid >> 3), c8 = tid & 7;
            *(uint4*)(Bs + row * SAY + c8 * 8) =
                *(const uint4*)(g_Wy + (size_t)row * HH + kc + c8 * 8);
        }
        __syncthreads();
        #pragma unroll
        for (int ks = 0; ks < 64; ks += 16) {
            const __half* Ap = As + R1 * SAY + ks + tg * 2;
            unsigned a0 = *(const unsigned*)(Ap);
            unsigned a1 = *(const unsigned*)(Ap + 8 * SAY);
            unsigned a2 = *(const unsigned*)(Ap + 8);
            unsigned a3 = *(const unsigned*)(Ap + 8 * SAY + 8);
            #pragma unroll
            for (int nt = 0; nt < 32; ++nt) {
                const __half* Bp = Bs + (nt * 8 + gq) * SAY + ks + tg * 2;
                mma16816(acc[nt], a0, a1, a2, a3,
                         *(const unsigned*)(Bp), *(const unsigned*)(Bp + 8));
            }
        }
        __syncthreads();
    }

    #pragma unroll
    for (int rr = 0; rr < 2; ++rr) {
        float m = -1e30f;
        #pragma unroll
        for (int nt = 0; nt < 32; ++nt)
            #pragma unroll
            for (int c = 0; c < 2; ++c) {
                float v = acc[nt][rr * 2 + c] + __ldg(&by[nt * 8 + tg * 2 + c]);
                acc[nt][rr * 2 + c] = v;
                m = fmaxf(m, v);
            }
        m = fmaxf(m, __shfl_xor_sync(0xffffffffu, m, 1));
        m = fmaxf(m, __shfl_xor_sync(0xffffffffu, m, 2));
        float s = 0.0f;
        #pragma unroll
        for (int nt = 0; nt < 32; ++nt)
            #pragma unroll
            for (int c = 0; c < 2; ++c) {
                float e = __expf(acc[nt][rr * 2 + c] - m);
                acc[nt][rr * 2 + c] = e;
                s += e;
            }
        s += __shfl_xor_sync(0xffffffffu, s, 1);
        s += __shfl_xor_sync(0xffffffffu, s, 2);
        float inv = 1.0f / s;
        int b = R1 + rr * 8;
        float* orow = out + ((size_t)b * TT + t) * NOUT;
        #pragma unroll
        for (int nt = 0; nt < 32; ++nt) {
            float2 pr = make_float2(acc[nt][rr * 2] * inv, acc[nt][rr * 2 + 1] * inv);
            *(float2*)(orow + nt * 8 + tg * 2) = pr;
        }
    }
}

// ---------------- launcher ----------------
extern "C" void kernel_launch(void* const* d_in, const int* in_sizes, int n_in,
                              void* d_out, int out_size)
{
    const float* u   = (const float*)d_in[0];
    const float* Wuf = (const float*)d_in[1];
    const float* Wui = (const float*)d_in[2];
    const float* Wuo = (const float*)d_in[3];
    const float* Wuc = (const float*)d_in[4];
    const float* Whf = (const float*)d_in[5];
    const float* Whi = (const float*)d_in[6];
    const float* Who = (const float*)d_in[7];
    const float* Whc = (const float*)d_in[8];
    const float* Why = (const float*)d_in[9];
    const float* bf  = (const float*)d_in[10];
    const float* bi  = (const float*)d_in[11];
    const float* bo  = (const float*)d_in[12];
    const float* bc  = (const float*)d_in[13];
    const float* by  = (const float*)d_in[14];
    const float* h0  = (const float*)d_in[15];
    float* out = (float*)d_out;

    cudaFuncSetAttribute(lstm_main, cudaFuncAttributeMaxDynamicSharedMemorySize, WBYTES);
    cudaFuncSetAttribute(y_kernel,  cudaFuncAttributeMaxDynamicSharedMemorySize, SMEM_Y);

    pack_wh_kernel<<<(NCTA * 32 * HH) / 256, 256>>>(Whf, Whi, Who, Whc);
    pack_wut_kernel<<<(NG * NIN) / 256, 256>>>(Wuf, Wui, Wuo, Wuc);
    pack_u_kernel<<<(BB * TT * NIN) / 256, 256>>>(u);
    pack_misc_kernel<<<1024, 256>>>(Why, h0);
    xgemm_kernel<<<dim3(NG / 128, TT), 256, XG_SMEM>>>(bf, bi, bo, bc);
    lstm_main<<<NCTA, 256, WBYTES>>>(h0);
    y_kernel<<<TT, 256, SMEM_Y>>>(by, out);
}

// round 11
// speedup vs baseline: 1.6301x; 1.2875x over previous
#include <cuda_runtime.h>
#include <cuda_fp16.h>

#define BB   128
#define TT   1024
#define NIN  512
#define HH   1024
#define NOUT 256
#define NG   4096
#define NCTA 128

#define WSTRIDE 1032                      // halves; 2064B rows (129 x 16B) LDSM conflict-free
#define WBYTES  (32 * WSTRIDE * 2)        // 66048
#define NCHUNK  16

#define SAY 72
#define SMEM_Y ((BB + NOUT) * SAY * 2)
#define XG_SMEM (2 * 128 * 72 * 2)

// ---------------- device scratch ----------------
__device__ __half  g_Wp [(size_t)NCTA * 32 * HH];        // recurrent W [cta][l=32][k=1024], k-PERMUTED
__device__ __half  g_WuT[(size_t)NG * NIN];              // input W^T [l][k]
__device__ __half  g_u16[(size_t)TT * BB * NIN];         // [t][b][n]
__device__ __half  g_histx[(size_t)(TT + 1) * BB * HH];  // h[0..TT], NATURAL column order
__device__ __half  g_Wy [(size_t)NOUT * HH];             // W_hy^T [n][k], natural
__device__ float   g_X  [(size_t)TT * NG * BB];          // u-gate pre-acts (+bias)
__device__ unsigned g_flag[(TT + 1) * 16];               // per (t, col-group) readiness 0->8

// W-side k permutation (involution on pairs within a 32-half block):
// storage pair q holds logical pair 4*(q&3) + (q>>2). h stays NATURAL; the
// lane's contiguous uint4 (logical pairs 4tg..4tg+3) then matches permuted-W
// B-fragments: ks0 -> (.x,.y), ks1 -> (.z,.w).
__device__ __forceinline__ int permk(int k) {
    int kp = (k >> 1) & 15;
    int tp = ((kp & 3) << 2) | (kp >> 2);
    return (k & ~31) | (tp << 1) | (k & 1);
}

// ---------------- ptx helpers ----------------
__device__ __forceinline__ unsigned smem_u32(const void* p) {
    unsigned a;
    asm("{ .reg .u64 t; cvta.to.shared.u64 t, %1; cvt.u32.u64 %0, t; }" : "=r"(a) : "l"(p));
    return a;
}
#define LDSM4(r0, r1, r2, r3, a) \
    asm volatile("ldmatrix.sync.aligned.m8n8.x4.shared.b16 {%0,%1,%2,%3}, [%4];" \
                 : "=r"(r0), "=r"(r1), "=r"(r2), "=r"(r3) : "r"((unsigned)(a)))

__device__ __forceinline__ void mma16816(float* c, unsigned a0, unsigned a1, unsigned a2, unsigned a3,
                                         unsigned b0, unsigned b1) {
    asm volatile(
        "mma.sync.aligned.m16n8k16.row.col.f32.f16.f16.f32 "
        "{%0,%1,%2,%3}, {%4,%5,%6,%7}, {%8,%9}, {%0,%1,%2,%3};"
        : "+f"(c[0]), "+f"(c[1]), "+f"(c[2]), "+f"(c[3])
        : "r"(a0), "r"(a1), "r"(a2), "r"(a3), "r"(b0), "r"(b1));
}
__device__ __forceinline__ float tanha(float x) {
    float r; asm("tanh.approx.f32 %0, %1;" : "=f"(r) : "f"(x)); return r;
}
__device__ __forceinline__ float siga(float x) { return 0.5f * tanha(0.5f * x) + 0.5f; }

__device__ __forceinline__ void wait_flag(const unsigned* p) {
    unsigned v;
    asm volatile("ld.acquire.gpu.global.u32 %0, [%1];" : "=r"(v) : "l"(p));
    if (v < 8u) {
        do {
            __nanosleep(32);
            asm volatile("ld.acquire.gpu.global.u32 %0, [%1];" : "=r"(v) : "l"(p));
        } while (v < 8u);
    }
}
__device__ __forceinline__ void release_flag(unsigned* p) {
    asm volatile("red.release.gpu.global.add.u32 [%0], %1;" :: "l"(p), "r"(1u) : "memory");
}

// ---------------- prep ----------------
__global__ void pack_wh_kernel(const float* __restrict__ Whf, const float* __restrict__ Whi,
                               const float* __restrict__ Who, const float* __restrict__ Whc)
{
    int idx = blockIdx.x * blockDim.x + threadIdx.x;
    if (idx >= NCTA * 32 * HH) return;
    int k = idx & (HH - 1);
    int l = (idx >> 10) & 31;
    int cta = idx >> 15;
    int g = (l >> 3) & 3;
    int j = cta * 8 + (l & 7);
    const float* W = (g == 0) ? Whf : (g == 1) ? Whi : (g == 2) ? Who : Whc;
    g_Wp[idx] = __float2half_rn(W[(size_t)permk(k) * HH + j]);   // ONLY W is k-permuted
}

__global__ void pack_wut_kernel(const float* __restrict__ Wuf, const float* __restrict__ Wui,
                                const float* __restrict__ Wuo, const float* __restrict__ Wuc)
{
    int idx = blockIdx.x * blockDim.x + threadIdx.x;
    if (idx >= NG * NIN) return;
    int k = idx & (NIN - 1);
    int l = idx >> 9;
    int g = (l >> 3) & 3;
    int j = (l >> 5) * 8 + (l & 7);
    const float* W = (g == 0) ? Wuf : (g == 1) ? Wui : (g == 2) ? Wuo : Wuc;
    g_WuT[idx] = __float2half_rn(W[(size_t)k * HH + j]);
}

__global__ void pack_u_kernel(const float* __restrict__ u)
{
    long long idx = (long long)blockIdx.x * blockDim.x + threadIdx.x;
    if (idx >= (long long)BB * TT * NIN) return;
    int n = (int)(idx & (NIN - 1));
    int t = (int)((idx >> 9) & (TT - 1));
    int b = (int)(idx >> 19);
    g_u16[((size_t)t * BB + b) * NIN + n] = __float2half_rn(u[idx]);
}

__global__ void pack_misc_kernel(const float* __restrict__ Why, const float* __restrict__ h0)
{
    int idx = blockIdx.x * blockDim.x + threadIdx.x;
    if (idx < NOUT * HH) {
        int n = idx / HH, k = idx % HH;
        g_Wy[idx] = __float2half_rn(Why[(size_t)k * NOUT + n]);   // natural
    }
    if (idx < BB * HH) {
        g_histx[idx] = __float2half_rn(h0[idx & (HH - 1)]);       // h[0] natural
    }
    if (idx < (TT + 1) * 16) {
        g_flag[idx] = (idx < 16) ? 8u : 0u;
    }
}

// ---------------- X GEMM: X[t][l][b] = sum_k WuT[l][k]*u[t][b][k] + bias[l] ----------------
__global__ void __launch_bounds__(256, 2)
xgemm_kernel(const float* __restrict__ bf, const float* __restrict__ bi,
             const float* __restrict__ bo, const float* __restrict__ bc)
{
    extern __shared__ char sm[];
    __half* As = (__half*)sm;                 // [128 l][72]
    __half* Bs = (__half*)sm + 128 * 72;      // [128 b][72]
    const unsigned asb = smem_u32(As), bsb = smem_u32(Bs);

    const int tid = threadIdx.x, w = tid >> 5, lane = tid & 31;
    const int gq = lane >> 2, tg = lane & 3;
    const int bx = blockIdx.x, t = blockIdx.y;
    const int i8 = lane & 7, sel = lane >> 3;
    const unsigned aLane = ((w * 16 + (lane & 15)) * 144) + ((lane >> 4) * 16);
    const unsigned bRowOff = ((((sel >> 1) & 1) * 8 + i8) * 144) + ((sel & 1) * 16);

    float acc[16][4];
    #pragma unroll
    for (int nt = 0; nt < 16; ++nt)
        #pragma unroll
        for (int e = 0; e < 4; ++e) acc[nt][e] = 0.0f;

    for (int kc = 0; kc < NIN; kc += 64) {
        #pragma unroll
        for (int p = 0; p < 4; ++p) {
            int row = p * 32 + (tid >> 3), c8 = tid & 7;
            *(uint4*)(As + row * 72 + c8 * 8) =
                *(const uint4*)(g_WuT + (size_t)(bx * 128 + row) * NIN + kc + c8 * 8);
            *(uint4*)(Bs + row * 72 + c8 * 8) =
                *(const uint4*)(g_u16 + ((size_t)t * BB + row) * NIN + kc + c8 * 8);
        }
        __syncthreads();
        #pragma unroll
        for (int ks = 0; ks < 4; ++ks) {
            unsigned a0, a1, a2, a3;
            LDSM4(a0, a1, a2, a3, asb + aLane + ks * 32);
            #pragma unroll
            for (int p = 0; p < 8; ++p) {
                unsigned r0, r1, r2, r3;
                LDSM4(r0, r1, r2, r3, bsb + p * (16 * 144) + bRowOff + ks * 32);
                mma16816(acc[p * 2 + 0], a0, a1, a2, a3, r0, r1);
                mma16816(acc[p * 2 + 1], a0, a1, a2, a3, r2, r3);
            }
        }
        __syncthreads();
    }

    const float* bsel[4] = {bf, bi, bo, bc};
    #pragma unroll
    for (int rr = 0; rr < 2; ++rr) {
        int l = bx * 128 + w * 16 + gq + rr * 8;
        int g = (l >> 3) & 3;
        float bv = bsel[g][(l >> 5) * 8 + (l & 7)];
        float* orow = g_X + ((size_t)t * NG + l) * BB;
        #pragma unroll
        for (int nt = 0; nt < 16; ++nt) {
            float2 v = make_float2(acc[nt][rr * 2] + bv, acc[nt][rr * 2 + 1] + bv);
            *(float2*)(orow + nt * 8 + tg * 2) = v;
        }
    }
}

// ---------------- persistent recurrent kernel ----------------
// 8 MMA warps. A-frags via LDG.128 from NATURAL h (one uint4 per lane per 32-k);
// W k-permuted so B-frags align; LDSM hoisted per chunk.
__global__ void __launch_bounds__(256, 1)
lstm_main(const float* __restrict__ h0)
{
    extern __shared__ char sm[];
    const unsigned smb = smem_u32(sm);
    const int tid = threadIdx.x, cta = blockIdx.x;
    const int w = tid >> 5, lane = tid & 31;
    const int gq = lane >> 2, tg = lane & 3;
    const int i8 = lane & 7, sel = lane >> 3;
    const unsigned bRowOff = ((((sel >> 1) & 1) * 8 + i8) * (WSTRIDE * 2)) + ((sel & 1) * 16);
    const int bb0 = w * 16 + gq;               // batch rows bb0, bb0+8
    const int j0  = cta * 8 + tg * 2;          // hidden cols (natural)
    const int c0  = cta >> 3;

    // resident recurrent W slice [32][1024] -> stride 1032 (k-permuted image)
    {
        const uint4* src = (const uint4*)(g_Wp + (size_t)cta * 32 * HH);
        for (int i = tid; i < 32 * 128; i += 256) {
            int r = i >> 7, c = i & 127;
            *(uint4*)((__half*)sm + r * WSTRIDE + c * 8) = src[(size_t)r * 128 + c];
        }
    }
    __syncthreads();

    float hold[2][2];
    hold[0][0] = hold[1][0] = h0[j0];
    hold[0][1] = hold[1][1] = h0[j0 + 1];

    for (int t = 0; t < TT; ++t) {
        const char* r0p = (const char*)(g_histx + (size_t)t * BB * HH + (size_t)bb0 * HH) + tg * 16;
        const char* r8p = r0p + 8 * (HH * 2);

        float acc[4][4];
        #pragma unroll
        for (int nt = 0; nt < 4; ++nt)
            #pragma unroll
            for (int e = 0; e < 4; ++e) acc[nt][e] = 0.0f;

        uint4 A[3][4];   // [buf][group*2 + row]: group = 32-k half of chunk, row in {gq, gq+8}
        #pragma unroll
        for (int pi = 0; pi < 2; ++pi) {
            int c = (c0 + pi) & 15;
            wait_flag(&g_flag[t * 16 + c]);
            const char* cb = r0p + c * 128;
            A[pi][0] = *(const uint4*)(cb);
            A[pi][1] = *(const uint4*)(r8p + c * 128);
            A[pi][2] = *(const uint4*)(cb + 64);
            A[pi][3] = *(const uint4*)(r8p + c * 128 + 64);
        }

        #pragma unroll
        for (int i = 0; i < NCHUNK; ++i) {
            if (i + 2 < NCHUNK) {
                int c = (c0 + i + 2) & 15;
                uint4* Ap = A[(i + 2) % 3];
                wait_flag(&g_flag[t * 16 + c]);
                const char* cb = r0p + c * 128;
                Ap[0] = *(const uint4*)(cb);
                Ap[1] = *(const uint4*)(r8p + c * 128);
                Ap[2] = *(const uint4*)(cb + 64);
                Ap[3] = *(const uint4*)(r8p + c * 128 + 64);
            }
            const uint4* Ac = A[i % 3];
            const unsigned kb = smb + bRowOff + (unsigned)(((c0 + i) & 15) * 128);

            unsigned br[4][4], bs[4][4];
            #pragma unroll
            for (int ks = 0; ks < 4; ++ks)
                LDSM4(br[ks][0], br[ks][1], br[ks][2], br[ks][3], kb + ks * 32);
            #pragma unroll
            for (int ks = 0; ks < 4; ++ks)
                LDSM4(bs[ks][0], bs[ks][1], bs[ks][2], bs[ks][3],
                      kb + 16 * (WSTRIDE * 2) + ks * 32);

            #pragma unroll
            for (int ks = 0; ks < 4; ++ks) {
                const uint4 q0 = Ac[(ks >> 1) * 2], q8 = Ac[(ks >> 1) * 2 + 1];
                unsigned a0, a1, a2, a3;
                if ((ks & 1) == 0) { a0 = q0.x; a1 = q8.x; a2 = q0.y; a3 = q8.y; }
                else               { a0 = q0.z; a1 = q8.z; a2 = q0.w; a3 = q8.w; }
                mma16816(acc[0], a0, a1, a2, a3, br[ks][0], br[ks][1]);
                mma16816(acc[1], a0, a1, a2, a3, br[ks][2], br[ks][3]);
                mma16816(acc[2], a0, a1, a2, a3, bs[ks][0], bs[ks][1]);
                mma16816(acc[3], a0, a1, a2, a3, bs[ks][2], bs[ks][3]);
            }
        }

        // X loads (issued while last MMA chains drain)
        float xr[16];
        #pragma unroll
        for (int g = 0; g < 4; ++g)
            #pragma unroll
            for (int cc = 0; cc < 2; ++cc)
                #pragma unroll
                for (int rr = 0; rr < 2; ++rr)
                    xr[g * 4 + cc * 2 + rr] =
                        g_X[((size_t)t * NG + cta * 32 + g * 8 + tg * 2 + cc) * BB + bb0 + rr * 8];

        // epilogue: gates (n-tiles are the 4 gates), register h_old, natural store
        __half* hw = g_histx + (size_t)(t + 1) * BB * HH;
        #pragma unroll
        for (int rr = 0; rr < 2; ++rr) {
            float hn[2];
            #pragma unroll
            for (int cc = 0; cc < 2; ++cc) {
                int e = rr * 2 + cc;
                float f  = siga (acc[0][e] + xr[0 * 4 + cc * 2 + rr]);
                float ii = siga (acc[1][e] + xr[1 * 4 + cc * 2 + rr]);
                float o  = siga (acc[2][e] + xr[2 * 4 + cc * 2 + rr]);
                float ct = tanha(acc[3][e] + xr[3 * 4 + cc * 2 + rr]);
                float cn = f * hold[rr][cc] + ii * ct;     // faithful: uses h, not c
                hn[cc] = o * tanha(cn);
                hold[rr][cc] = hn[cc];
            }
            *(__half2*)(hw + (size_t)(bb0 + rr * 8) * HH + j0) = __floats2half2_rn(hn[0], hn[1]);
        }

        __syncthreads();
        if (tid == 0) release_flag(&g_flag[(t + 1) * 16 + (cta >> 3)]);
    }
}

// ---------------- output pass: y = softmax(hist @ Wy + by) ----------------
__global__ void __launch_bounds__(256, 1)
y_kernel(const float* __restrict__ by, float* __restrict__ out)
{
    extern __shared__ char sm[];
    __half* As = (__half*)sm;
    __half* Bs = (__half*)sm + BB * SAY;

    const int tid = threadIdx.x, w = tid >> 5, lane = tid & 31;
    const int gq = lane >> 2, tg = lane & 3;
    const int t = blockIdx.x;
    const size_t rowbase = (size_t)(t + 1) * BB;            // y_t from h[t+1]
    const int R1 = w * 16 + gq;

    float acc[32][4];
    #pragma unroll
    for (int nt = 0; nt < 32; ++nt)
        #pragma unroll
        for (int e = 0; e < 4; ++e) acc[nt][e] = 0.0f;

    for (int kc = 0; kc < HH; kc += 64) {
        #pragma unroll
        for (int p = 0; p < 4; ++p) {
            int row = p * 32 + (tid >> 3), c8 = tid & 7;
            *(uint4*)(As + row * SAY + c8 * 8) =
                *(const uint4*)(g_histx + (rowbase + row) * HH + kc + c8 * 8);
        }
        #pragma unroll
        for (int p = 0; p < 8; ++p) {
            int row = p * 32 + (tid >> 3), c8 = tid & 7;
            *(uint4*)(Bs + row * SAY + c8 * 8) =
                *(const uint4*)(g_Wy + (size_t)row * HH + kc + c8 * 8);
        }
        __syncthreads();
        #pragma unroll
        for (int ks = 0; ks < 64; ks += 16) {
            const __half* Ap = As + R1 * SAY + ks + tg * 2;
            unsigned a0 = *(const unsigned*)(Ap);
            unsigned a1 = *(const unsigned*)(Ap + 8 * SAY);
            unsigned a2 = *(const unsigned*)(Ap + 8);
            unsigned a3 = *(const unsigned*)(Ap + 8 * SAY + 8);
            #pragma unroll
            for (int nt = 0; nt < 32; ++nt) {
                const __half* Bp = Bs + (nt * 8 + gq) * SAY + ks + tg * 2;
                mma16816(acc[nt], a0, a1, a2, a3,
                         *(const unsigned*)(Bp), *(const unsigned*)(Bp + 8));
            }
        }
        __syncthreads();
    }

    #pragma unroll
    for (int rr = 0; rr < 2; ++rr) {
        float m = -1e30f;
        #pragma unroll
        for (int nt = 0; nt < 32; ++nt)
            #pragma unroll
            for (int c = 0; c < 2; ++c) {
                float v = acc[nt][rr * 2 + c] + __ldg(&by[nt * 8 + tg * 2 + c]);
                acc[nt][rr * 2 + c] = v;
                m = fmaxf(m, v);
            }
        m = fmaxf(m, __shfl_xor_sync(0xffffffffu, m, 1));
        m = fmaxf(m, __shfl_xor_sync(0xffffffffu, m, 2));
        float s = 0.0f;
        #pragma unroll
        for (int nt = 0; nt < 32; ++nt)
            #pragma unroll
            for (int c = 0; c < 2; ++c) {
                float e = __expf(acc[nt][rr * 2 + c] - m);
                acc[nt][rr * 2 + c] = e;
                s += e;
            }
        s += __shfl_xor_sync(0xffffffffu, s, 1);
        s += __shfl_xor_sync(0xffffffffu, s, 2);
        float inv = 1.0f / s;
        int b = R1 + rr * 8;
        float* orow = out + ((size_t)b * TT + t) * NOUT;
        #pragma unroll
        for (int nt = 0; nt < 32; ++nt) {
            float2 pr = make_float2(acc[nt][rr * 2] * inv, acc[nt][rr * 2 + 1] * inv);
            *(float2*)(orow + nt * 8 + tg * 2) = pr;
        }
    }
}

// ---------------- launcher ----------------
extern "C" void kernel_launch(void* const* d_in, const int* in_sizes, int n_in,
                              void* d_out, int out_size)
{
    const float* u   = (const float*)d_in[0];
    const float* Wuf = (const float*)d_in[1];
    const float* Wui = (const float*)d_in[2];
    const float* Wuo = (const float*)d_in[3];
    const float* Wuc = (const float*)d_in[4];
    const float* Whf = (const float*)d_in[5];
    const float* Whi = (const float*)d_in[6];
    const float* Who = (const float*)d_in[7];
    const float* Whc = (const float*)d_in[8];
    const float* Why = (const float*)d_in[9];
    const float* bf  = (const float*)d_in[10];
    const float* bi  = (const float*)d_in[11];
    const float* bo  = (const float*)d_in[12];
    const float* bc  = (const float*)d_in[13];
    const float* by  = (const float*)d_in[14];
    const float* h0  = (const float*)d_in[15];
    float* out = (float*)d_out;

    cudaFuncSetAttribute(lstm_main, cudaFuncAttributeMaxDynamicSharedMemorySize, WBYTES);
    cudaFuncSetAttribute(y_kernel,  cudaFuncAttributeMaxDynamicSharedMemorySize, SMEM_Y);

    pack_wh_kernel<<<(NCTA * 32 * HH) / 256, 256>>>(Whf, Whi, Who, Whc);
    pack_wut_kernel<<<(NG * NIN) / 256, 256>>>(Wuf, Wui, Wuo, Wuc);
    pack_u_kernel<<<(BB * TT * NIN) / 256, 256>>>(u);
    pack_misc_kernel<<<1024, 256>>>(Why, h0);
    xgemm_kernel<<<dim3(NG / 128, TT), 256, XG_SMEM>>>(bf, bi, bo, bc);
    lstm_main<<<NCTA, 256, WBYTES>>>(h0);
    y_kernel<<<TT, 256, SMEM_Y>>>(by, out);
}